// round 2
// baseline (speedup 1.0000x reference)
#include <cuda_runtime.h>
#include <math.h>

#define Dm 512
#define Cm 256
#define Bm 8
#define Lm 4096
#define TOKS (Bm*Lm)
#define TM 16
#define NT 256
#define SX 520
#define SH 1032

// SMEM floats: 4 buffers *TM*SX + TM*SH + Cm + 3*Dm + 4*TM + TM
#define SMEM_FLOATS (4*TM*SX + TM*SH + Cm + 3*Dm + 5*TM)
#define SMEM_BYTES (SMEM_FLOATS*4)

// ---------------- device scratch (no runtime allocation allowed) ----------------
__device__ float g_w1f[1024*1536];   // folded mix_w1
__device__ float g_gam[Bm*Dm];       // 1 + gamma
__device__ float g_bet[Bm*Dm];
__device__ float g_gate[Bm*Dm];
__device__ float g_Kc[Bm*2*Dm];
__device__ float g_Vc[Bm*2*Dm];

// ---------------- fold mix_w1: [Wa|Wb|Wc|Wd] (K=2048) -> [Wa+Wc | Wb-Wc | Wd] (K=1536)
__global__ void fold_kernel(const float* __restrict__ w1) {
    int idx = blockIdx.x*blockDim.x + threadIdx.x;
    if (idx >= 1024*1536) return;
    int j = idx / 1536, k = idx - j*1536;
    const float* row = w1 + (size_t)j*2048;
    float v;
    if (k < 512)       v = row[k] + row[1024+k];      // Wa + Wc
    else if (k < 1024) v = row[k] - row[512+k];       // Wb - Wc
    else               v = row[512+k];                // Wd
    g_w1f[idx] = v;
}

// ---------------- per-batch context pipeline ----------------
__global__ void ctx_kernel(const float* __restrict__ ctx,
    const float* __restrict__ film_w, const float* __restrict__ film_b,
    const float* __restrict__ w1, const float* __restrict__ b1,
    const float* __restrict__ w2, const float* __restrict__ b2,
    const float* __restrict__ inw, const float* __restrict__ inb,
    const float* __restrict__ gw, const float* __restrict__ gb)
{
    __shared__ float sc[Cm];
    __shared__ float sh[512];
    __shared__ float st[1024];
    int b = blockIdx.x, tid = threadIdx.x;
    if (tid < Cm) sc[tid] = ctx[b*Cm + tid];
    __syncthreads();
    for (int j = tid; j < 1024; j += NT) {
        const float* w = film_w + (size_t)j*Cm;
        float s = film_b[j];
        #pragma unroll 4
        for (int c = 0; c < Cm; c++) s = fmaf(w[c], sc[c], s);
        if (j < 512) g_gam[b*512 + j] = 1.f + s;
        else         g_bet[b*512 + (j-512)] = s;
    }
    for (int d = tid; d < 512; d += NT) {
        const float* w = gw + (size_t)d*Cm;
        float s = gb[d];
        #pragma unroll 4
        for (int c = 0; c < Cm; c++) s = fmaf(w[c], sc[c], s);
        g_gate[b*512 + d] = 1.f/(1.f + expf(-s));
    }
    for (int i = tid; i < 512; i += NT) {
        const float* w = w1 + (size_t)i*Cm;
        float s = b1[i];
        #pragma unroll 4
        for (int c = 0; c < Cm; c++) s = fmaf(w[c], sc[c], s);
        sh[i] = 0.5f*s*(1.f + erff(s*0.70710678118654752f));   // exact gelu
    }
    __syncthreads();
    for (int m = tid; m < 1024; m += NT) {
        const float* w = w2 + (size_t)m*512;
        float s = b2[m];
        #pragma unroll 4
        for (int e = 0; e < 512; e++) s = fmaf(w[e], sh[e], s);
        st[m] = s;
    }
    __syncthreads();
    for (int d = tid; d < 512; d += NT) {
        const float* wk = inw + (size_t)(512 + d)*512;
        const float* wv = inw + (size_t)(1024 + d)*512;
        float k0 = inb[512 + d], k1 = k0;
        float v0 = inb[1024 + d], v1 = v0;
        #pragma unroll 4
        for (int e = 0; e < 512; e++) {
            float a = wk[e], c = wv[e];
            k0 = fmaf(a, st[e],     k0);
            k1 = fmaf(a, st[512+e], k1);
            v0 = fmaf(c, st[e],     v0);
            v1 = fmaf(c, st[512+e], v1);
        }
        g_Kc[(b*2+0)*512 + d] = k0; g_Kc[(b*2+1)*512 + d] = k1;
        g_Vc[(b*2+0)*512 + d] = v0; g_Vc[(b*2+1)*512 + d] = v1;
    }
}

// ---------------- helpers ----------------
__device__ __forceinline__ float dot4f(float4 w, float4 a) {
    return fmaf(w.x, a.x, fmaf(w.y, a.y, fmaf(w.z, a.z, w.w*a.w)));
}

__device__ __forceinline__ void lnstats(const float* __restrict__ S, int stride,
                                        float* __restrict__ mu, float* __restrict__ rs, int tid) {
    int warp = tid >> 5, lane = tid & 31;
    for (int t = warp; t < TM; t += 8) {
        const float* row = S + t*stride;
        float s = 0.f, s2 = 0.f;
        for (int k = lane; k < Dm; k += 32) { float v = row[k]; s += v; s2 = fmaf(v, v, s2); }
        #pragma unroll
        for (int o = 16; o; o >>= 1) {
            s  += __shfl_xor_sync(0xffffffffu, s,  o);
            s2 += __shfl_xor_sync(0xffffffffu, s2, o);
        }
        if (lane == 0) {
            float m = s*(1.f/Dm);
            float var = s2*(1.f/Dm) - m*m;
            mu[t] = m; rs[t] = rsqrtf(var + 1e-5f);
        }
    }
}

// Generic fused GEMM tile: 16 tokens x 512 outputs, act in smem, W row-major (n,ldw)
__device__ __forceinline__ void gemm_NK(
    const float* __restrict__ W, int ldw, int K,
    const float* __restrict__ bias,
    const float* __restrict__ sAct, int as,
    float* __restrict__ sOut, int os,
    int tg, int ng, bool relu)
{
    float acc[4][8];
    #pragma unroll
    for (int i = 0; i < 4; i++)
        #pragma unroll
        for (int j = 0; j < 8; j++) acc[i][j] = 0.f;
    #pragma unroll 2
    for (int k = 0; k < K; k += 4) {
        float4 a0 = *(const float4*)(sAct + (tg     )*as + k);
        float4 a1 = *(const float4*)(sAct + (tg +  4)*as + k);
        float4 a2 = *(const float4*)(sAct + (tg +  8)*as + k);
        float4 a3 = *(const float4*)(sAct + (tg + 12)*as + k);
        #pragma unroll
        for (int jj = 0; jj < 8; jj++) {
            float4 w = *(const float4*)(W + (size_t)(ng + (jj<<6))*ldw + k);
            acc[0][jj] += dot4f(w, a0);
            acc[1][jj] += dot4f(w, a1);
            acc[2][jj] += dot4f(w, a2);
            acc[3][jj] += dot4f(w, a3);
        }
    }
    #pragma unroll
    for (int jj = 0; jj < 8; jj++) {
        int n = ng + (jj<<6);
        float bb = bias[n];
        #pragma unroll
        for (int i = 0; i < 4; i++) {
            float v = acc[i][jj] + bb;
            if (relu) v = fmaxf(v, 0.f);
            sOut[(tg + (i<<2))*os + n] = v;
        }
    }
}

// ---------------- main fused per-token kernel (16 tokens / CTA) ----------------
__global__ void __launch_bounds__(NT)
main_kernel(const float* __restrict__ x, const float* __restrict__ ctx,
    const unsigned int* __restrict__ mask,
    const float* __restrict__ fg, const float* __restrict__ fb,
    const float* __restrict__ cw, const float* __restrict__ cbias,
    const float* __restrict__ cg, const float* __restrict__ cb,
    const float* __restrict__ qg, const float* __restrict__ qb,
    const float* __restrict__ inw, const float* __restrict__ inb,
    const float* __restrict__ opw, const float* __restrict__ opb,
    const float* __restrict__ mb1, const float* __restrict__ w2, const float* __restrict__ mb2,
    const float* __restrict__ og, const float* __restrict__ ob,
    float* __restrict__ out)
{
    extern __shared__ float sm[];
    float* XS   = sm;                 // [16][520] x tile
    float* UC   = XS + TM*SX;         // upd_c
    float* QA   = UC + TM*SX;         // x_q -> attn a -> upd_a -> pre-LN out
    float* AO   = QA + TM*SX;         // attn_out
    float* H1   = AO + TM*SX;         // [16][1032] q scratch, then mix hidden
    float* SCTX = H1 + TM*SH;         // [256]
    float* SGAM = SCTX + Cm;          // [512] (1+gamma)
    float* SBET = SGAM + Dm;
    float* SGATE= SBET + Dm;
    float* MU   = SGATE + Dm;         // x stats
    float* RS   = MU + TM;
    float* MU2  = RS + TM;            // reusable stats
    float* RS2  = MU2 + TM;
    float* MSK  = RS2 + TM;

    const int tid  = threadIdx.x;
    const int tok0 = blockIdx.x * TM;
    const int b    = tok0 >> 12;      // tok0 / 4096
    const int tg   = tid & 3;         // tokens tg, tg+4, tg+8, tg+12
    const int ng   = tid >> 2;        // 64 output groups

    // load x tile + per-batch vectors
    for (int idx = tid; idx < TM*(Dm/4); idx += NT) {
        int t = idx >> 7, kk = (idx & 127) << 2;
        *(float4*)(XS + t*SX + kk) = *(const float4*)(x + (size_t)(tok0 + t)*Dm + kk);
    }
    if (tid < Cm) SCTX[tid] = ctx[b*Cm + tid];
    for (int d0 = tid; d0 < Dm; d0 += NT) {
        SGAM[d0]  = g_gam[b*Dm + d0];
        SBET[d0]  = g_bet[b*Dm + d0];
        SGATE[d0] = g_gate[b*Dm + d0];
    }
    // mask: 4-byte elements (works for both float32 1.0f/0.0f and int32 1/0)
    if (tid < TM) MSK[tid] = (mask[tok0 + tid] != 0u) ? 1.f : 0.f;
    __syncthreads();

    lnstats(XS, SX, MU, RS, tid);
    __syncthreads();

    // ---- GEMM1: concat proj, K = 512 (x) + 256 (ctx), relu -> UC ----
    {
        float acc[4][8];
        #pragma unroll
        for (int i = 0; i < 4; i++)
            #pragma unroll
            for (int j = 0; j < 8; j++) acc[i][j] = 0.f;
        #pragma unroll 2
        for (int k = 0; k < 512; k += 4) {
            float4 a0 = *(const float4*)(XS + (tg     )*SX + k);
            float4 a1 = *(const float4*)(XS + (tg +  4)*SX + k);
            float4 a2 = *(const float4*)(XS + (tg +  8)*SX + k);
            float4 a3 = *(const float4*)(XS + (tg + 12)*SX + k);
            #pragma unroll
            for (int jj = 0; jj < 8; jj++) {
                float4 w = *(const float4*)(cw + (size_t)(ng + (jj<<6))*768 + k);
                acc[0][jj] += dot4f(w, a0);
                acc[1][jj] += dot4f(w, a1);
                acc[2][jj] += dot4f(w, a2);
                acc[3][jj] += dot4f(w, a3);
            }
        }
        #pragma unroll 2
        for (int k = 0; k < 256; k += 4) {
            float4 c4 = *(const float4*)(SCTX + k);
            #pragma unroll
            for (int jj = 0; jj < 8; jj++) {
                float4 w = *(const float4*)(cw + (size_t)(ng + (jj<<6))*768 + 512 + k);
                float s = dot4f(w, c4);
                acc[0][jj] += s; acc[1][jj] += s; acc[2][jj] += s; acc[3][jj] += s;
            }
        }
        #pragma unroll
        for (int jj = 0; jj < 8; jj++) {
            int n = ng + (jj<<6);
            float bb = cbias[n];
            #pragma unroll
            for (int i = 0; i < 4; i++)
                UC[(tg + (i<<2))*SX + n] = fmaxf(acc[i][jj] + bb, 0.f);
        }
    }
    __syncthreads();
    lnstats(UC, SX, MU2, RS2, tid);
    __syncthreads();
    // concat-LN in place; also build x_q into QA (reuses x stats)
    for (int idx = tid; idx < TM*Dm; idx += NT) {
        int t = idx >> 9, n = idx & 511;
        float v = UC[t*SX + n];
        UC[t*SX + n] = (v - MU2[t])*RS2[t]*cg[n] + cb[n];
        QA[t*SX + n] = (XS[t*SX + n] - MU[t])*RS[t]*qg[n] + qb[n];
    }
    __syncthreads();

    // ---- GEMM2: q = wq @ x_q + bq  -> H1 ----
    gemm_NK(inw, Dm, Dm, inb, QA, SX, H1, SH, tg, ng, false);
    __syncthreads();

    // ---- attention over T=2 context tokens, H=2 heads -> a into QA ----
    {
        int warp = tid >> 5, lane = tid & 31;
        for (int it = warp; it < TM*2; it += 8) {
            int t = it >> 1, h = it & 1;
            const float* qrow = H1 + t*SH + h*256;
            const float* K0 = g_Kc + (b*2+0)*Dm + h*256;
            const float* K1 = g_Kc + (b*2+1)*Dm + h*256;
            float s0 = 0.f, s1 = 0.f;
            for (int dd = lane; dd < 256; dd += 32) {
                float qv = qrow[dd];
                s0 = fmaf(qv, K0[dd], s0);
                s1 = fmaf(qv, K1[dd], s1);
            }
            #pragma unroll
            for (int o = 16; o; o >>= 1) {
                s0 += __shfl_xor_sync(0xffffffffu, s0, o);
                s1 += __shfl_xor_sync(0xffffffffu, s1, o);
            }
            s0 *= 0.0625f; s1 *= 0.0625f;   // 1/sqrt(256)
            float m = fmaxf(s0, s1);
            float e0 = expf(s0 - m), e1 = expf(s1 - m);
            float inv = 1.f/(e0 + e1);
            float p0 = e0*inv, p1 = e1*inv;
            const float* V0 = g_Vc + (b*2+0)*Dm + h*256;
            const float* V1 = g_Vc + (b*2+1)*Dm + h*256;
            for (int dd = lane; dd < 256; dd += 32)
                QA[t*SX + h*256 + dd] = p0*V0[dd] + p1*V1[dd];
        }
    }
    __syncthreads();

    // ---- GEMM3: attn_out = out_proj @ a + b -> AO ----
    gemm_NK(opw, Dm, Dm, opb, QA, SX, AO, SX, tg, ng, false);
    __syncthreads();

    // ---- GEMM4: mix hidden with folded weights (K=1536: x, ao, x*ao) -> H1, relu ----
    for (int p = 0; p < 2; p++) {
        float acc[4][8];
        #pragma unroll
        for (int i = 0; i < 4; i++)
            #pragma unroll
            for (int j = 0; j < 8; j++) acc[i][j] = 0.f;
        #pragma unroll 1
        for (int k = 0; k < 512; k += 4) {
            float4 xa[4], oa[4], pa[4];
            #pragma unroll
            for (int i = 0; i < 4; i++) {
                xa[i] = *(const float4*)(XS + (tg + (i<<2))*SX + k);
                oa[i] = *(const float4*)(AO + (tg + (i<<2))*SX + k);
                pa[i].x = xa[i].x*oa[i].x; pa[i].y = xa[i].y*oa[i].y;
                pa[i].z = xa[i].z*oa[i].z; pa[i].w = xa[i].w*oa[i].w;
            }
            #pragma unroll
            for (int jj = 0; jj < 8; jj++) {
                const float* r = g_w1f + (size_t)(p*512 + ng + (jj<<6))*1536;
                float4 wa = *(const float4*)(r + k);
                float4 wb = *(const float4*)(r + 512 + k);
                float4 wd = *(const float4*)(r + 1024 + k);
                #pragma unroll
                for (int i = 0; i < 4; i++)
                    acc[i][jj] += dot4f(wa, xa[i]) + dot4f(wb, oa[i]) + dot4f(wd, pa[i]);
            }
        }
        #pragma unroll
        for (int jj = 0; jj < 8; jj++) {
            int n = p*512 + ng + (jj<<6);
            float bb = mb1[n];
            #pragma unroll
            for (int i = 0; i < 4; i++)
                H1[(tg + (i<<2))*SH + n] = fmaxf(acc[i][jj] + bb, 0.f);
        }
        __syncthreads();
    }

    // ---- GEMM5: upd_a = mix_w2 @ h1 + mb2 -> QA ----
    gemm_NK(w2, 1024, 1024, mb2, H1, SH, QA, SX, tg, ng, false);
    __syncthreads();

    // ---- combine: base + gate*mask*(upd_c + upd_a), then final LN ----
    for (int idx = tid; idx < TM*Dm; idx += NT) {
        int t = idx >> 9, n = idx & 511;
        float upd  = QA[t*SX + n] + UC[t*SX + n];
        float xhat = (XS[t*SX + n] - MU[t])*RS[t];
        float base = SGAM[n]*fmaf(xhat, fg[n], fb[n]) + SBET[n];
        QA[t*SX + n] = base + SGATE[n]*MSK[t]*upd;
    }
    __syncthreads();
    lnstats(QA, SX, MU2, RS2, tid);
    __syncthreads();
    for (int idx = tid; idx < TM*Dm; idx += NT) {
        int t = idx >> 9, n = idx & 511;
        out[(size_t)(tok0 + t)*Dm + n] = (QA[t*SX + n] - MU2[t])*RS2[t]*og[n] + ob[n];
    }
}

// ---------------- launch ----------------
extern "C" void kernel_launch(void* const* d_in, const int* in_sizes, int n_in,
                              void* d_out, int out_size) {
    const float* x          = (const float*)d_in[0];
    const float* context    = (const float*)d_in[1];
    const unsigned int* mask = (const unsigned int*)d_in[2];
    const float* film_ln_g  = (const float*)d_in[3];
    const float* film_ln_b  = (const float*)d_in[4];
    const float* film_w     = (const float*)d_in[5];
    const float* film_b     = (const float*)d_in[6];
    const float* concat_w   = (const float*)d_in[7];
    const float* concat_b   = (const float*)d_in[8];
    const float* concat_ln_g= (const float*)d_in[9];
    const float* concat_ln_b= (const float*)d_in[10];
    const float* ctx_w1     = (const float*)d_in[11];
    const float* ctx_b1     = (const float*)d_in[12];
    const float* ctx_w2     = (const float*)d_in[13];
    const float* ctx_b2     = (const float*)d_in[14];
    const float* q_ln_g     = (const float*)d_in[15];
    const float* q_ln_b     = (const float*)d_in[16];
    const float* in_proj_w  = (const float*)d_in[17];
    const float* in_proj_b  = (const float*)d_in[18];
    const float* out_proj_w = (const float*)d_in[19];
    const float* out_proj_b = (const float*)d_in[20];
    const float* mix_w1     = (const float*)d_in[21];
    const float* mix_b1     = (const float*)d_in[22];
    const float* mix_w2     = (const float*)d_in[23];
    const float* mix_b2     = (const float*)d_in[24];
    const float* out_ln_g   = (const float*)d_in[25];
    const float* out_ln_b   = (const float*)d_in[26];
    const float* gate_w     = (const float*)d_in[27];
    const float* gate_b     = (const float*)d_in[28];
    float* out = (float*)d_out;

    fold_kernel<<<(1024*1536 + NT - 1)/NT, NT>>>(mix_w1);
    ctx_kernel<<<Bm, NT>>>(context, film_w, film_b, ctx_w1, ctx_b1, ctx_w2, ctx_b2,
                           in_proj_w, in_proj_b, gate_w, gate_b);
    cudaFuncSetAttribute(main_kernel, cudaFuncAttributeMaxDynamicSharedMemorySize, SMEM_BYTES);
    main_kernel<<<TOKS/TM, NT, SMEM_BYTES>>>(x, context, mask,
        film_ln_g, film_ln_b, concat_w, concat_b, concat_ln_g, concat_ln_b,
        q_ln_g, q_ln_b, in_proj_w, in_proj_b, out_proj_w, out_proj_b,
        mix_b1, mix_w2, mix_b2, out_ln_g, out_ln_b, out);
}

// round 11
// speedup vs baseline: 2.5102x; 2.5102x over previous
#include <cuda_runtime.h>
#include <cuda_bf16.h>
#include <cstdint>
#include <math.h>

#define MT 32768
#define Cm 256
#define Bm 8

// ===================== helpers =====================
#define MMA_BF16(C, A, B) asm volatile( \
    "mma.sync.aligned.m16n8k16.row.col.f32.bf16.bf16.f32 " \
    "{%0,%1,%2,%3}, {%4,%5,%6,%7}, {%8,%9}, {%0,%1,%2,%3};" \
    : "+f"((C)[0]), "+f"((C)[1]), "+f"((C)[2]), "+f"((C)[3]) \
    : "r"((A)[0]), "r"((A)[1]), "r"((A)[2]), "r"((A)[3]), "r"((B)[0]), "r"((B)[1]))

__device__ __forceinline__ void split2(float v, __nv_bfloat16& h, __nv_bfloat16& l) {
    h = __float2bfloat16(v);
    l = __float2bfloat16(v - __bfloat162float(h));
}
__device__ __forceinline__ uint32_t pk(__nv_bfloat16 a, __nv_bfloat16 b) {
    __nv_bfloat162 t = __halves2bfloat162(a, b);   // a = lower k col
    return reinterpret_cast<uint32_t&>(t);
}

// ===================== device global scratch (ALL fp32) =====================
__device__ float g_xq[MT*512];
__device__ float g_q[MT*512];
__device__ float g_a[MT*512];
__device__ float g_ao[MT*512];
__device__ float g_d[MT*512];    // x - ao
__device__ float g_p[MT*512];    // x * ao
__device__ float g_h[MT*1024];
__device__ float g_t[MT*1024];   // G4 partial accumulator
__device__ float g_t2[MT*512];   // G5 partial accumulator
__device__ float g_ucpre[MT*512], g_ucn[MT*512], g_pre[MT*512];
__device__ float g_mu[MT], g_rs[MT];
__device__ float g_cbF[Bm*512], g_gam[Bm*512], g_bet[Bm*512], g_gate[Bm*512];
__device__ float g_Kc[Bm*2*512], g_Vc[Bm*2*512];

// ===================== per-batch context pipeline (R2-validated math) =====================
__global__ void ctx_kernel_v11(const float* __restrict__ ctx,
    const float* __restrict__ film_w, const float* __restrict__ film_b,
    const float* __restrict__ w1, const float* __restrict__ b1,
    const float* __restrict__ w2, const float* __restrict__ b2,
    const float* __restrict__ inw, const float* __restrict__ inb,
    const float* __restrict__ gw, const float* __restrict__ gb,
    const float* __restrict__ cw, const float* __restrict__ cb)
{
    __shared__ float sc[Cm];
    __shared__ float sh[512];
    __shared__ float st[1024];
    int b = blockIdx.x, tid = threadIdx.x;
    if (tid < Cm) sc[tid] = ctx[b*Cm + tid];
    __syncthreads();
    for (int j = tid; j < 1024; j += 256) {
        const float* w = film_w + (size_t)j*Cm;
        float s = film_b[j];
        #pragma unroll 4
        for (int c = 0; c < Cm; c++) s = fmaf(w[c], sc[c], s);
        if (j < 512) g_gam[b*512 + j] = 1.f + s;
        else         g_bet[b*512 + (j-512)] = s;
    }
    for (int d = tid; d < 512; d += 256) {
        const float* w = gw + (size_t)d*Cm;
        float s = gb[d];
        #pragma unroll 4
        for (int c = 0; c < Cm; c++) s = fmaf(w[c], sc[c], s);
        g_gate[b*512 + d] = 1.f/(1.f + expf(-s));
    }
    for (int n = tid; n < 512; n += 256) {
        const float* w = cw + (size_t)n*768 + 512;
        float s = cb[n];
        #pragma unroll 4
        for (int c = 0; c < Cm; c++) s = fmaf(w[c], sc[c], s);
        g_cbF[b*512 + n] = s;
    }
    for (int i = tid; i < 512; i += 256) {
        const float* w = w1 + (size_t)i*Cm;
        float s = b1[i];
        #pragma unroll 4
        for (int c = 0; c < Cm; c++) s = fmaf(w[c], sc[c], s);
        sh[i] = 0.5f*s*(1.f + erff(s*0.70710678118654752f));
    }
    __syncthreads();
    for (int m = tid; m < 1024; m += 256) {
        const float* w = w2 + (size_t)m*512;
        float s = b2[m];
        #pragma unroll 4
        for (int e = 0; e < 512; e++) s = fmaf(w[e], sh[e], s);
        st[m] = s;
    }
    __syncthreads();
    for (int d = tid; d < 512; d += 256) {
        const float* wk = inw + (size_t)(512 + d)*512;
        const float* wv = inw + (size_t)(1024 + d)*512;
        float k0 = inb[512 + d], k1 = k0;
        float v0 = inb[1024 + d], v1 = v0;
        #pragma unroll 4
        for (int e = 0; e < 512; e++) {
            float a = wk[e], c = wv[e];
            k0 = fmaf(a, st[e],     k0);
            k1 = fmaf(a, st[512+e], k1);
            v0 = fmaf(c, st[e],     v0);
            v1 = fmaf(c, st[512+e], v1);
        }
        g_Kc[(b*2+0)*512 + d] = k0; g_Kc[(b*2+1)*512 + d] = k1;
        g_Vc[(b*2+0)*512 + d] = v0; g_Vc[(b*2+1)*512 + d] = v1;
    }
}

// ===================== prologue: LN stats + x_q =====================
__global__ void prep_x_v11(const float* __restrict__ x,
                           const float* __restrict__ qg, const float* __restrict__ qb)
{
    int tok = blockIdx.x*8 + (threadIdx.x >> 5);
    int lane = threadIdx.x & 31;
    const float* row = x + (size_t)tok*512;
    float v[16];
    float s = 0.f, s2 = 0.f;
    #pragma unroll
    for (int i = 0; i < 16; i++) { v[i] = row[lane + i*32]; s += v[i]; s2 = fmaf(v[i], v[i], s2); }
    #pragma unroll
    for (int o = 16; o; o >>= 1) {
        s  += __shfl_xor_sync(0xffffffffu, s,  o);
        s2 += __shfl_xor_sync(0xffffffffu, s2, o);
    }
    float m = s*(1.f/512.f);
    float r = rsqrtf(s2*(1.f/512.f) - m*m + 1e-5f);
    if (lane == 0) { g_mu[tok] = m; g_rs[tok] = r; }
    #pragma unroll
    for (int i = 0; i < 16; i++) {
        int k = lane + i*32;
        g_xq[(size_t)tok*512 + k] = (v[i] - m)*r*qg[k] + qb[k];
    }
}

// ===================== standalone attention (R2-validated) =====================
__global__ void attn_kernel_v11()
{
    int wid = threadIdx.x >> 5, lane = threadIdx.x & 31;
    int tok = blockIdx.x*4 + (wid >> 1);
    int h   = wid & 1;
    int b   = tok >> 12;
    const float* qrow = g_q + (size_t)tok*512 + h*256;
    const float* K0 = g_Kc + (size_t)(b*2+0)*512 + h*256;
    const float* K1 = g_Kc + (size_t)(b*2+1)*512 + h*256;
    float s0 = 0.f, s1 = 0.f;
    for (int d = lane; d < 256; d += 32) {
        float qv = qrow[d];
        s0 = fmaf(qv, K0[d], s0);
        s1 = fmaf(qv, K1[d], s1);
    }
    #pragma unroll
    for (int o = 16; o; o >>= 1) {
        s0 += __shfl_xor_sync(0xffffffffu, s0, o);
        s1 += __shfl_xor_sync(0xffffffffu, s1, o);
    }
    s0 *= 0.0625f; s1 *= 0.0625f;
    float mx = fmaxf(s0, s1);
    float e0 = expf(s0 - mx), e1 = expf(s1 - mx);
    float inv = 1.f/(e0 + e1);
    float p0 = e0*inv, p1 = e1*inv;
    const float* V0 = g_Vc + (size_t)(b*2+0)*512 + h*256;
    const float* V1 = g_Vc + (size_t)(b*2+1)*512 + h*256;
    for (int d = lane; d < 256; d += 32)
        g_a[(size_t)tok*512 + h*256 + d] = p0*V0[d] + p1*V1[d];
}

// ===================== elementwise: d = x - ao, p = x*ao =====================
__global__ void dp_kernel_v11(const float* __restrict__ x)
{
    size_t i = (size_t)blockIdx.x*256 + threadIdx.x;
    float xv = x[i], av = g_ao[i];
    g_d[i] = xv - av;
    g_p[i] = xv * av;
}

// ===================== LN kernels =====================
template<int W>
__global__ void ln_kernel_v11(const float* __restrict__ gv, const float* __restrict__ bv, float* __restrict__ outp)
{
    int tok = blockIdx.x*8 + (threadIdx.x >> 5);
    int lane = threadIdx.x & 31;
    const float* in = (W == 0) ? g_ucpre : g_pre;
    float* out = (W == 0) ? g_ucn : outp;
    const float* row = in + (size_t)tok*512;
    float v[16];
    float s = 0.f, s2 = 0.f;
    #pragma unroll
    for (int i = 0; i < 16; i++) { v[i] = row[lane + i*32]; s += v[i]; s2 = fmaf(v[i], v[i], s2); }
    #pragma unroll
    for (int o = 16; o; o >>= 1) {
        s  += __shfl_xor_sync(0xffffffffu, s,  o);
        s2 += __shfl_xor_sync(0xffffffffu, s2, o);
    }
    float m = s*(1.f/512.f);
    float r = rsqrtf(s2*(1.f/512.f) - m*m + 1e-5f);
    #pragma unroll
    for (int i = 0; i < 16; i++) {
        int k = lane + i*32;
        out[(size_t)tok*512 + k] = (v[i] - m)*r*gv[k] + bv[k];
    }
}

// ===================== UNIFORM warp-MMA GEMM slice: K=512 ALWAYS (validated G1 shape) =====================
// M=128 x N=256 tile, NCH=8, single-buffer, fp32 load + hi/lo split. Row 144B.
#define RB      144
#define OFF_A   0
#define APLANE  (128*RB)
#define OFF_B   (2*APLANE)
#define BPLANE  (256*RB)
#define OFF_EPI (OFF_B + 2*BPLANE)
#define GSMEM   (OFF_EPI + 1536*4 + 256)

// EPI: 1=UC(relu+cbF->ucpre) 2=Q 3=AO 4=WRITE(pOut=acc) 7=ADD(pOut+=acc)
//      5=HRELU(pOut=relu(prev+acc+bias), canary) 6=FINAL(combine)
template<int EPI, int BSTR, int AROW, int OSTR, int NOFF>
__global__ void __launch_bounds__(256, 1)
gemm_v11(const float* __restrict__ pA, const float* __restrict__ pB,
         const float* __restrict__ bias, float* __restrict__ pOut,
         const float* __restrict__ prev, const float* __restrict__ xp,
         const unsigned int* __restrict__ pm,
         const float* __restrict__ flng, const float* __restrict__ flnb)
{
    extern __shared__ char smem[];
    float* sEpi = (float*)(smem + OFF_EPI);

    const int tid = threadIdx.x;
    const int wid = tid >> 5, lane = tid & 31;
    const int gid = lane >> 2, tg = lane & 3;
    const int wm = wid >> 2, wn = wid & 3;
    const int tok0 = blockIdx.x * 128;
    const int n0   = NOFF + blockIdx.y * 256;
    const int b    = tok0 >> 12;

    float acc[4][8][4];
    #pragma unroll
    for (int mt = 0; mt < 4; mt++)
        #pragma unroll
        for (int nt = 0; nt < 8; nt++)
            #pragma unroll
            for (int r = 0; r < 4; r++) acc[mt][nt][r] = 0.f;

    for (int c = 0; c < 8; c++) {
        const int kb = c*64;
        __syncthreads();
        // A: 128 rows x 64 fp32 -> hi/lo planes
        #pragma unroll
        for (int it = 0; it < 8; it++) {
            int u = tid + it*256;
            int r = u >> 4, q = u & 15;
            float4 va = *(const float4*)(pA + (size_t)(tok0 + r)*AROW + kb + q*4);
            __nv_bfloat16 h0,l0,h1,l1,h2,l2,h3,l3;
            split2(va.x,h0,l0); split2(va.y,h1,l1); split2(va.z,h2,l2); split2(va.w,h3,l3);
            uint32_t off = (uint32_t)(r*RB + q*8);
            *(uint2*)(smem + OFF_A + off)          = make_uint2(pk(h0,h1), pk(h2,h3));
            *(uint2*)(smem + OFF_A + APLANE + off) = make_uint2(pk(l0,l1), pk(l2,l3));
        }
        // B: 256 rows x 64 fp32 -> hi/lo planes
        #pragma unroll
        for (int it = 0; it < 16; it++) {
            int u = tid + it*256;
            int r = u >> 4, q = u & 15;
            float4 vb = *(const float4*)(pB + (size_t)(n0 + r)*BSTR + kb + q*4);
            __nv_bfloat16 h0,l0,h1,l1,h2,l2,h3,l3;
            split2(vb.x,h0,l0); split2(vb.y,h1,l1); split2(vb.z,h2,l2); split2(vb.w,h3,l3);
            uint32_t off = (uint32_t)(r*RB + q*8);
            *(uint2*)(smem + OFF_B + off)          = make_uint2(pk(h0,h1), pk(h2,h3));
            *(uint2*)(smem + OFF_B + BPLANE + off) = make_uint2(pk(l0,l1), pk(l2,l3));
        }
        __syncthreads();

        #pragma unroll
        for (int ks = 0; ks < 64; ks += 16) {
            uint32_t bh[8][2], bl[8][2];
            #pragma unroll
            for (int nt = 0; nt < 8; nt++) {
                uint32_t o0 = OFF_B + (uint32_t)(wn*64 + nt*8 + gid)*RB + (ks + tg*2)*2;
                uint32_t o1 = o0 + BPLANE;
                bh[nt][0] = *(const uint32_t*)(smem + o0);
                bh[nt][1] = *(const uint32_t*)(smem + o0 + 16);
                bl[nt][0] = *(const uint32_t*)(smem + o1);
                bl[nt][1] = *(const uint32_t*)(smem + o1 + 16);
            }
            #pragma unroll
            for (int mt = 0; mt < 4; mt++) {
                uint32_t oh = OFF_A + (uint32_t)(wm*64 + mt*16 + gid)*RB + (ks + tg*2)*2;
                uint32_t ol = oh + APLANE;
                uint32_t ah[4], al[4];
                ah[0] = *(const uint32_t*)(smem + oh);
                ah[1] = *(const uint32_t*)(smem + oh + 8*RB);
                ah[2] = *(const uint32_t*)(smem + oh + 16);
                ah[3] = *(const uint32_t*)(smem + oh + 8*RB + 16);
                al[0] = *(const uint32_t*)(smem + ol);
                al[1] = *(const uint32_t*)(smem + ol + 8*RB);
                al[2] = *(const uint32_t*)(smem + ol + 16);
                al[3] = *(const uint32_t*)(smem + ol + 8*RB + 16);
                #pragma unroll
                for (int nt = 0; nt < 8; nt++) {
                    MMA_BF16(acc[mt][nt], ah, bh[nt]);
                    MMA_BF16(acc[mt][nt], ah, bl[nt]);
                    MMA_BF16(acc[mt][nt], al, bh[nt]);
                }
            }
        }
    }
    __syncthreads();

    // epilogue preloads
    if (EPI == 1) {
        if (tid < 256) sEpi[tid] = g_cbF[b*512 + n0 + tid];
    } else if (EPI == 2 || EPI == 3 || EPI == 5) {
        if (tid < 256) sEpi[tid] = bias[n0 + tid];
    } else if (EPI == 6) {
        if (tid < 256) {
            sEpi[tid]        = bias[n0 + tid];           // mix_b2
            sEpi[256 + tid]  = g_gam[b*512 + n0 + tid];
            sEpi[512 + tid]  = g_bet[b*512 + n0 + tid];
            sEpi[768 + tid]  = g_gate[b*512 + n0 + tid];
            sEpi[1024 + tid] = flng[n0 + tid];
            sEpi[1280 + tid] = flnb[n0 + tid];
        }
    }
    __syncthreads();

    #pragma unroll
    for (int mt = 0; mt < 4; mt++) {
        #pragma unroll
        for (int rh = 0; rh < 2; rh++) {
            int tok = tok0 + wm*64 + mt*16 + gid + rh*8;
            float muv = 0.f, rsv = 0.f, mskv = 0.f;
            if (EPI == 6) {
                muv = g_mu[tok]; rsv = g_rs[tok];
                mskv = (pm[tok] != 0u) ? 1.f : 0.f;
            }
            #pragma unroll
            for (int nt = 0; nt < 8; nt++) {
                #pragma unroll
                for (int rb = 0; rb < 2; rb++) {
                    int nl = wn*64 + nt*8 + tg*2 + rb;
                    float av = acc[mt][nt][rh*2 + rb];
                    if (EPI == 1) {
                        g_ucpre[(size_t)tok*512 + n0 + nl] = fmaxf(av + sEpi[nl], 0.f);
                    } else if (EPI == 2) {
                        g_q[(size_t)tok*512 + n0 + nl] = av + sEpi[nl];
                    } else if (EPI == 3) {
                        g_ao[(size_t)tok*512 + n0 + nl] = av + sEpi[nl];
                    } else if (EPI == 4) {
                        pOut[(size_t)tok*OSTR + n0 + nl] = av;
                    } else if (EPI == 7) {
                        pOut[(size_t)tok*OSTR + n0 + nl] += av;
                    } else if (EPI == 5) {
                        size_t gi = (size_t)tok*OSTR + n0 + nl;
                        float v = prev[gi] + av + sEpi[nl];
                        if (v != v) v = 1e20f;                 // NaN canary
                        else        v = fmaxf(v, 0.f);
                        pOut[gi] = v;
                    } else {  // EPI 6: final combine
                        size_t gi = (size_t)tok*512 + n0 + nl;
                        float ua = prev[gi] + av + sEpi[nl];
                        float xv = xp[gi];
                        float xh = (xv - muv)*rsv;
                        float base = sEpi[256 + nl]*fmaf(xh, sEpi[1024 + nl], sEpi[1280 + nl]) + sEpi[512 + nl];
                        g_pre[gi] = base + sEpi[768 + nl]*mskv*(g_ucn[gi] + ua);
                    }
                }
            }
        }
    }
}

// ===================== launch =====================
extern "C" void kernel_launch(void* const* d_in, const int* in_sizes, int n_in,
                              void* d_out, int out_size) {
    const float* x          = (const float*)d_in[0];
    const float* context    = (const float*)d_in[1];
    const unsigned int* mask = (const unsigned int*)d_in[2];
    const float* film_ln_g  = (const float*)d_in[3];
    const float* film_ln_b  = (const float*)d_in[4];
    const float* film_w     = (const float*)d_in[5];
    const float* film_b     = (const float*)d_in[6];
    const float* concat_w   = (const float*)d_in[7];
    const float* concat_b   = (const float*)d_in[8];
    const float* concat_ln_g= (const float*)d_in[9];
    const float* concat_ln_b= (const float*)d_in[10];
    const float* ctx_w1     = (const float*)d_in[11];
    const float* ctx_b1     = (const float*)d_in[12];
    const float* ctx_w2     = (const float*)d_in[13];
    const float* ctx_b2     = (const float*)d_in[14];
    const float* q_ln_g     = (const float*)d_in[15];
    const float* q_ln_b     = (const float*)d_in[16];
    const float* in_proj_w  = (const float*)d_in[17];
    const float* in_proj_b  = (const float*)d_in[18];
    const float* out_proj_w = (const float*)d_in[19];
    const float* out_proj_b = (const float*)d_in[20];
    const float* mix_w1     = (const float*)d_in[21];
    const float* mix_b1     = (const float*)d_in[22];
    const float* mix_w2     = (const float*)d_in[23];
    const float* mix_b2     = (const float*)d_in[24];
    const float* out_ln_g   = (const float*)d_in[25];
    const float* out_ln_b   = (const float*)d_in[26];
    const float* gate_w     = (const float*)d_in[27];
    const float* gate_b     = (const float*)d_in[28];
    float* out = (float*)d_out;

    float* t_ptr;  cudaGetSymbolAddress((void**)&t_ptr,  g_t);
    float* t2_ptr; cudaGetSymbolAddress((void**)&t2_ptr, g_t2);
    float* h_ptr;  cudaGetSymbolAddress((void**)&h_ptr,  g_h);
    float* xq_ptr; cudaGetSymbolAddress((void**)&xq_ptr, g_xq);
    float* a_ptr;  cudaGetSymbolAddress((void**)&a_ptr,  g_a);
    float* ao_ptr; cudaGetSymbolAddress((void**)&ao_ptr, g_ao);
    float* d_ptr;  cudaGetSymbolAddress((void**)&d_ptr,  g_d);
    float* p_ptr;  cudaGetSymbolAddress((void**)&p_ptr,  g_p);

    #define SETSM(K) cudaFuncSetAttribute(K, cudaFuncAttributeMaxDynamicSharedMemorySize, GSMEM)
    SETSM((gemm_v11<1,768,512,512,0>));
    SETSM((gemm_v11<2,512,512,512,0>));
    SETSM((gemm_v11<3,512,512,512,0>));
    SETSM((gemm_v11<4,2048,512,1024,0>));   SETSM((gemm_v11<4,2048,512,1024,512>));
    SETSM((gemm_v11<7,2048,512,1024,0>));   SETSM((gemm_v11<7,2048,512,1024,512>));
    SETSM((gemm_v11<5,2048,512,1024,0>));   SETSM((gemm_v11<5,2048,512,1024,512>));
    SETSM((gemm_v11<4,1024,1024,512,0>));
    SETSM((gemm_v11<6,1024,1024,512,0>));

    ctx_kernel_v11<<<Bm, 256>>>(context, film_w, film_b, ctx_w1, ctx_b1, ctx_w2, ctx_b2,
                                in_proj_w, in_proj_b, gate_w, gate_b, concat_w, concat_b);
    prep_x_v11<<<MT/8, 256>>>(x, q_ln_g, q_ln_b);

    dim3 G(256, 2);
    // G1: ucpre = relu(x @ Wcx^T + cbF)
    gemm_v11<1,768,512,512,0><<<G, 256, GSMEM>>>(x, concat_w, nullptr, nullptr, nullptr, nullptr, nullptr, nullptr, nullptr);
    ln_kernel_v11<0><<<MT/8, 256>>>(concat_ln_g, concat_ln_b, nullptr);
    // G2: q
    gemm_v11<2,512,512,512,0><<<G, 256, GSMEM>>>(xq_ptr, in_proj_w, in_proj_b, nullptr, nullptr, nullptr, nullptr, nullptr, nullptr);
    attn_kernel_v11<<<MT/4, 256>>>();
    // G3: ao
    gemm_v11<3,512,512,512,0><<<G, 256, GSMEM>>>(a_ptr, out_proj_w, out_proj_b, nullptr, nullptr, nullptr, nullptr, nullptr, nullptr);
    // d = x-ao, p = x*ao
    dp_kernel_v11<<<(MT*512)/256, 256>>>(x);

    // G4: h = relu(sum_s A_s @ W1_s^T + mb1), 4 K-slices x 2 N-halves (all K=512 shape)
    const float* Asrc[4] = { x, ao_ptr, d_ptr, p_ptr };
    for (int s = 0; s < 4; s++) {
        const float* As = Asrc[s];
        const float* Bs = mix_w1 + s*512;
        if (s == 0) {
            gemm_v11<4,2048,512,1024,0>  <<<G, 256, GSMEM>>>(As, Bs, nullptr, t_ptr, nullptr, nullptr, nullptr, nullptr, nullptr);
            gemm_v11<4,2048,512,1024,512><<<G, 256, GSMEM>>>(As, Bs, nullptr, t_ptr, nullptr, nullptr, nullptr, nullptr, nullptr);
        } else if (s < 3) {
            gemm_v11<7,2048,512,1024,0>  <<<G, 256, GSMEM>>>(As, Bs, nullptr, t_ptr, nullptr, nullptr, nullptr, nullptr, nullptr);
            gemm_v11<7,2048,512,1024,512><<<G, 256, GSMEM>>>(As, Bs, nullptr, t_ptr, nullptr, nullptr, nullptr, nullptr, nullptr);
        } else {
            gemm_v11<5,2048,512,1024,0>  <<<G, 256, GSMEM>>>(As, Bs, mix_b1, h_ptr, t_ptr, nullptr, nullptr, nullptr, nullptr);
            gemm_v11<5,2048,512,1024,512><<<G, 256, GSMEM>>>(As, Bs, mix_b1, h_ptr, t_ptr, nullptr, nullptr, nullptr, nullptr);
        }
    }
    // G5: 2 K-slices; slice1 carries final combine
    gemm_v11<4,1024,1024,512,0><<<G, 256, GSMEM>>>(h_ptr, mix_w2, nullptr, t2_ptr, nullptr, nullptr, nullptr, nullptr, nullptr);
    gemm_v11<6,1024,1024,512,0><<<G, 256, GSMEM>>>(h_ptr + 512, mix_w2 + 512, mix_b2, nullptr, t2_ptr, x, mask, film_ln_g, film_ln_b);
    // final LN
    ln_kernel_v11<1><<<MT/8, 256>>>(out_ln_g, out_ln_b, out);
}

// round 12
// speedup vs baseline: 2.6138x; 1.0412x over previous
#include <cuda_runtime.h>
#include <cuda_bf16.h>
#include <cstdint>
#include <math.h>

#define MT 32768
#define Cm 256
#define Bm 8

// ===================== helpers =====================
__device__ __forceinline__ uint32_t smem_u32(const void* p) {
    uint32_t a;
    asm("{ .reg .u64 t; cvta.to.shared.u64 t, %1; cvt.u32.u64 %0, t; }" : "=r"(a) : "l"(p));
    return a;
}
__device__ __forceinline__ void cpa16(uint32_t s, const void* g) {
    asm volatile("cp.async.cg.shared.global [%0], [%1], 16;" :: "r"(s), "l"(g));
}
#define CP_COMMIT() asm volatile("cp.async.commit_group;" ::: "memory")
#define CP_WAIT0()  asm volatile("cp.async.wait_group 0;" ::: "memory")

#define MMA_BF16(C, A, B) asm volatile( \
    "mma.sync.aligned.m16n8k16.row.col.f32.bf16.bf16.f32 " \
    "{%0,%1,%2,%3}, {%4,%5,%6,%7}, {%8,%9}, {%0,%1,%2,%3};" \
    : "+f"((C)[0]), "+f"((C)[1]), "+f"((C)[2]), "+f"((C)[3]) \
    : "r"((A)[0]), "r"((A)[1]), "r"((A)[2]), "r"((A)[3]), "r"((B)[0]), "r"((B)[1]))

__device__ __forceinline__ void split2(float v, __nv_bfloat16& h, __nv_bfloat16& l) {
    h = __float2bfloat16(v);
    l = __float2bfloat16(v - __bfloat162float(h));
}
__device__ __forceinline__ uint32_t pk(__nv_bfloat16 a, __nv_bfloat16 b) {
    __nv_bfloat162 t = __halves2bfloat162(a, b);   // a = lower k col
    return reinterpret_cast<uint32_t&>(t);
}

// ===================== device global scratch =====================
__device__ float g_xq[MT*512];
__device__ float g_q[MT*512];
__device__ float g_a[MT*512];
__device__ float g_ao[MT*512];
__device__ float g_d[MT*512];    // x - ao
__device__ float g_p[MT*512];    // x * ao
__device__ float g_h[MT*1024];
__device__ float g_t[MT*1024];   // G4 partial accumulator
__device__ float g_t2[MT*512];   // G5 partial accumulator
__device__ float g_ucpre[MT*512], g_ucn[MT*512], g_pre[MT*512];
__device__ float g_mu[MT], g_rs[MT];
__device__ float g_cbF[Bm*512], g_gam[Bm*512], g_bet[Bm*512], g_gate[Bm*512];
__device__ float g_Kc[Bm*2*512], g_Vc[Bm*2*512];
// preprocessed bf16 hi/lo weights
__device__ __nv_bfloat16 g_wcxh[512*512], g_wcxl[512*512];
__device__ __nv_bfloat16 g_wqh[512*512],  g_wql[512*512];
__device__ __nv_bfloat16 g_woh[512*512],  g_wol[512*512];
__device__ __nv_bfloat16 g_w1h[1024*2048], g_w1l[1024*2048];
__device__ __nv_bfloat16 g_w2h[512*1024],  g_w2l[512*1024];

// ===================== weight preprocessing =====================
__global__ void split_plain_v12(const float* __restrict__ src, __nv_bfloat16* hi, __nv_bfloat16* lo, int n) {
    int i = blockIdx.x*blockDim.x + threadIdx.x;
    if (i >= n) return;
    split2(src[i], hi[i], lo[i]);
}
__global__ void split_cwx_v12(const float* __restrict__ cw) {  // concat_w x-part [512][768] -> [512][512]
    int i = blockIdx.x*blockDim.x + threadIdx.x;
    if (i >= 512*512) return;
    int r = i >> 9, c = i & 511;
    split2(cw[r*768 + c], g_wcxh[i], g_wcxl[i]);
}

// ===================== per-batch context pipeline (R2-validated) =====================
__global__ void ctx_kernel_v12(const float* __restrict__ ctx,
    const float* __restrict__ film_w, const float* __restrict__ film_b,
    const float* __restrict__ w1, const float* __restrict__ b1,
    const float* __restrict__ w2, const float* __restrict__ b2,
    const float* __restrict__ inw, const float* __restrict__ inb,
    const float* __restrict__ gw, const float* __restrict__ gb,
    const float* __restrict__ cw, const float* __restrict__ cb)
{
    __shared__ float sc[Cm];
    __shared__ float sh[512];
    __shared__ float st[1024];
    int b = blockIdx.x, tid = threadIdx.x;
    if (tid < Cm) sc[tid] = ctx[b*Cm + tid];
    __syncthreads();
    for (int j = tid; j < 1024; j += 256) {
        const float* w = film_w + (size_t)j*Cm;
        float s = film_b[j];
        #pragma unroll 4
        for (int c = 0; c < Cm; c++) s = fmaf(w[c], sc[c], s);
        if (j < 512) g_gam[b*512 + j] = 1.f + s;
        else         g_bet[b*512 + (j-512)] = s;
    }
    for (int d = tid; d < 512; d += 256) {
        const float* w = gw + (size_t)d*Cm;
        float s = gb[d];
        #pragma unroll 4
        for (int c = 0; c < Cm; c++) s = fmaf(w[c], sc[c], s);
        g_gate[b*512 + d] = 1.f/(1.f + expf(-s));
    }
    for (int n = tid; n < 512; n += 256) {
        const float* w = cw + (size_t)n*768 + 512;
        float s = cb[n];
        #pragma unroll 4
        for (int c = 0; c < Cm; c++) s = fmaf(w[c], sc[c], s);
        g_cbF[b*512 + n] = s;
    }
    for (int i = tid; i < 512; i += 256) {
        const float* w = w1 + (size_t)i*Cm;
        float s = b1[i];
        #pragma unroll 4
        for (int c = 0; c < Cm; c++) s = fmaf(w[c], sc[c], s);
        sh[i] = 0.5f*s*(1.f + erff(s*0.70710678118654752f));
    }
    __syncthreads();
    for (int m = tid; m < 1024; m += 256) {
        const float* w = w2 + (size_t)m*512;
        float s = b2[m];
        #pragma unroll 4
        for (int e = 0; e < 512; e++) s = fmaf(w[e], sh[e], s);
        st[m] = s;
    }
    __syncthreads();
    for (int d = tid; d < 512; d += 256) {
        const float* wk = inw + (size_t)(512 + d)*512;
        const float* wv = inw + (size_t)(1024 + d)*512;
        float k0 = inb[512 + d], k1 = k0;
        float v0 = inb[1024 + d], v1 = v0;
        #pragma unroll 4
        for (int e = 0; e < 512; e++) {
            float a = wk[e], c = wv[e];
            k0 = fmaf(a, st[e],     k0);
            k1 = fmaf(a, st[512+e], k1);
            v0 = fmaf(c, st[e],     v0);
            v1 = fmaf(c, st[512+e], v1);
        }
        g_Kc[(b*2+0)*512 + d] = k0; g_Kc[(b*2+1)*512 + d] = k1;
        g_Vc[(b*2+0)*512 + d] = v0; g_Vc[(b*2+1)*512 + d] = v1;
    }
}

// ===================== prologue: LN stats + x_q =====================
__global__ void prep_x_v12(const float* __restrict__ x,
                           const float* __restrict__ qg, const float* __restrict__ qb)
{
    int tok = blockIdx.x*8 + (threadIdx.x >> 5);
    int lane = threadIdx.x & 31;
    const float* row = x + (size_t)tok*512;
    float v[16];
    float s = 0.f, s2 = 0.f;
    #pragma unroll
    for (int i = 0; i < 16; i++) { v[i] = row[lane + i*32]; s += v[i]; s2 = fmaf(v[i], v[i], s2); }
    #pragma unroll
    for (int o = 16; o; o >>= 1) {
        s  += __shfl_xor_sync(0xffffffffu, s,  o);
        s2 += __shfl_xor_sync(0xffffffffu, s2, o);
    }
    float m = s*(1.f/512.f);
    float r = rsqrtf(s2*(1.f/512.f) - m*m + 1e-5f);
    if (lane == 0) { g_mu[tok] = m; g_rs[tok] = r; }
    #pragma unroll
    for (int i = 0; i < 16; i++) {
        int k = lane + i*32;
        g_xq[(size_t)tok*512 + k] = (v[i] - m)*r*qg[k] + qb[k];
    }
}

// ===================== standalone attention (R2-validated) =====================
__global__ void attn_kernel_v12()
{
    int wid = threadIdx.x >> 5, lane = threadIdx.x & 31;
    int tok = blockIdx.x*4 + (wid >> 1);
    int h   = wid & 1;
    int b   = tok >> 12;
    const float* qrow = g_q + (size_t)tok*512 + h*256;
    const float* K0 = g_Kc + (size_t)(b*2+0)*512 + h*256;
    const float* K1 = g_Kc + (size_t)(b*2+1)*512 + h*256;
    float s0 = 0.f, s1 = 0.f;
    for (int d = lane; d < 256; d += 32) {
        float qv = qrow[d];
        s0 = fmaf(qv, K0[d], s0);
        s1 = fmaf(qv, K1[d], s1);
    }
    #pragma unroll
    for (int o = 16; o; o >>= 1) {
        s0 += __shfl_xor_sync(0xffffffffu, s0, o);
        s1 += __shfl_xor_sync(0xffffffffu, s1, o);
    }
    s0 *= 0.0625f; s1 *= 0.0625f;
    float mx = fmaxf(s0, s1);
    float e0 = expf(s0 - mx), e1 = expf(s1 - mx);
    float inv = 1.f/(e0 + e1);
    float p0 = e0*inv, p1 = e1*inv;
    const float* V0 = g_Vc + (size_t)(b*2+0)*512 + h*256;
    const float* V1 = g_Vc + (size_t)(b*2+1)*512 + h*256;
    for (int d = lane; d < 256; d += 32)
        g_a[(size_t)tok*512 + h*256 + d] = p0*V0[d] + p1*V1[d];
}

// ===================== elementwise: d = x - ao, p = x*ao =====================
__global__ void dp_kernel_v12(const float* __restrict__ x)
{
    size_t i = (size_t)blockIdx.x*256 + threadIdx.x;
    float xv = x[i], av = g_ao[i];
    g_d[i] = xv - av;
    g_p[i] = xv * av;
}

// ===================== LN kernels =====================
template<int W>
__global__ void ln_kernel_v12(const float* __restrict__ gv, const float* __restrict__ bv, float* __restrict__ outp)
{
    int tok = blockIdx.x*8 + (threadIdx.x >> 5);
    int lane = threadIdx.x & 31;
    const float* in = (W == 0) ? g_ucpre : g_pre;
    float* out = (W == 0) ? g_ucn : outp;
    const float* row = in + (size_t)tok*512;
    float v[16];
    float s = 0.f, s2 = 0.f;
    #pragma unroll
    for (int i = 0; i < 16; i++) { v[i] = row[lane + i*32]; s += v[i]; s2 = fmaf(v[i], v[i], s2); }
    #pragma unroll
    for (int o = 16; o; o >>= 1) {
        s  += __shfl_xor_sync(0xffffffffu, s,  o);
        s2 += __shfl_xor_sync(0xffffffffu, s2, o);
    }
    float m = s*(1.f/512.f);
    float r = rsqrtf(s2*(1.f/512.f) - m*m + 1e-5f);
    #pragma unroll
    for (int i = 0; i < 16; i++) {
        int k = lane + i*32;
        out[(size_t)tok*512 + k] = (v[i] - m)*r*gv[k] + bv[k];
    }
}

// ===================== pipelined warp-MMA GEMM slice: K=512, chunk=32, double-buffered =====================
// Row = 32 bf16 (64B) + 16B pad = 80B.
#define RB2     80
#define APL     (128*RB2)
#define BPL     (256*RB2)
#define OFF_A   0
#define OFF_B   (4*APL)
#define OFF_EPI (OFF_B + 4*BPL)
#define GSMEM   (OFF_EPI + 1536*4 + 256)

// EPI: 1=UC 2=Q 3=AO 4=WRITE 7=ADD 5=HRELU(prev+acc+bias, canary) 6=FINAL
template<int EPI, int BSTR, int AROW, int OSTR, int NOFF>
__global__ void __launch_bounds__(256, 1)
gemm_v12(const float* __restrict__ pA,
         const __nv_bfloat16* __restrict__ pBh, const __nv_bfloat16* __restrict__ pBl,
         const float* __restrict__ bias, float* __restrict__ pOut,
         const float* __restrict__ prev, const float* __restrict__ xp,
         const unsigned int* __restrict__ pm,
         const float* __restrict__ flng, const float* __restrict__ flnb)
{
    extern __shared__ char smem[];
    uint32_t sb = smem_u32(smem);
    float* sEpi = (float*)(smem + OFF_EPI);

    const int tid = threadIdx.x;
    const int wid = tid >> 5, lane = tid & 31;
    const int gid = lane >> 2, tg = lane & 3;
    const int wm = wid >> 2, wn = wid & 3;
    const int tok0 = blockIdx.x * 128;
    const int n0   = NOFF + blockIdx.y * 256;
    const int b    = tok0 >> 12;

    // per-thread A slice indices (128 rows x 8 float4 per chunk -> 4 float4/thread)
    const int ar0 = tid >> 3, aq0 = tid & 7;   // +it*32 rows

    float acc[4][8][4];
    #pragma unroll
    for (int mt = 0; mt < 4; mt++)
        #pragma unroll
        for (int nt = 0; nt < 8; nt++)
            #pragma unroll
            for (int r = 0; r < 4; r++) acc[mt][nt][r] = 0.f;

    auto issueB = [&](int c, int buf) {
        const int kb = c*32;
        #pragma unroll
        for (int it = 0; it < 8; it++) {
            int u = tid + it*256;
            int p = u >> 10, rest = u & 1023;
            int r = rest >> 2, q = rest & 3;
            const __nv_bfloat16* src = (p ? pBl : pBh) + (size_t)(n0 + r)*BSTR + kb + q*8;
            cpa16(sb + OFF_B + (uint32_t)(buf*2*BPL + p*BPL + r*RB2 + q*16), src);
        }
        CP_COMMIT();
    };
    auto loadA = [&](int c, float4* areg) {
        const int kb = c*32;
        #pragma unroll
        for (int it = 0; it < 4; it++)
            areg[it] = *(const float4*)(pA + (size_t)(tok0 + ar0 + it*32)*AROW + kb + aq0*4);
    };
    auto storeA = [&](int buf, const float4* areg) {
        #pragma unroll
        for (int it = 0; it < 4; it++) {
            float4 va = areg[it];
            __nv_bfloat16 h0,l0,h1,l1,h2,l2,h3,l3;
            split2(va.x,h0,l0); split2(va.y,h1,l1); split2(va.z,h2,l2); split2(va.w,h3,l3);
            uint32_t off = (uint32_t)(buf*2*APL + (ar0 + it*32)*RB2 + aq0*8);
            *(uint2*)(smem + OFF_A + off)       = make_uint2(pk(h0,h1), pk(h2,h3));
            *(uint2*)(smem + OFF_A + APL + off) = make_uint2(pk(l0,l1), pk(l2,l3));
        }
    };

    // prologue: chunk 0 into buf 0
    {
        float4 areg[4];
        loadA(0, areg);
        issueB(0, 0);
        storeA(0, areg);
    }

    for (int c = 0; c < 16; c++) {
        const int buf = c & 1;
        CP_WAIT0();
        __syncthreads();            // buf(c) fully ready; prior compute done

        float4 areg[4];
        if (c < 15) {
            issueB(c+1, buf^1);     // async, overlaps compute
            loadA(c+1, areg);       // LDG latency hidden under compute below
        }

        #pragma unroll
        for (int ks = 0; ks < 32; ks += 16) {
            uint32_t bh[8][2], bl[8][2];
            #pragma unroll
            for (int nt = 0; nt < 8; nt++) {
                uint32_t o0 = OFF_B + (uint32_t)(buf*2*BPL + (wn*64 + nt*8 + gid)*RB2 + (ks + tg*2)*2);
                uint32_t o1 = o0 + BPL;
                bh[nt][0] = *(const uint32_t*)(smem + o0);
                bh[nt][1] = *(const uint32_t*)(smem + o0 + 16);
                bl[nt][0] = *(const uint32_t*)(smem + o1);
                bl[nt][1] = *(const uint32_t*)(smem + o1 + 16);
            }
            #pragma unroll
            for (int mt = 0; mt < 4; mt++) {
                uint32_t oh = OFF_A + (uint32_t)(buf*2*APL + (wm*64 + mt*16 + gid)*RB2 + (ks + tg*2)*2);
                uint32_t ol = oh + APL;
                uint32_t ah[4], al[4];
                ah[0] = *(const uint32_t*)(smem + oh);
                ah[1] = *(const uint32_t*)(smem + oh + 8*RB2);
                ah[2] = *(const uint32_t*)(smem + oh + 16);
                ah[3] = *(const uint32_t*)(smem + oh + 8*RB2 + 16);
                al[0] = *(const uint32_t*)(smem + ol);
                al[1] = *(const uint32_t*)(smem + ol + 8*RB2);
                al[2] = *(const uint32_t*)(smem + ol + 16);
                al[3] = *(const uint32_t*)(smem + ol + 8*RB2 + 16);
                #pragma unroll
                for (int nt = 0; nt < 8; nt++) {
                    MMA_BF16(acc[mt][nt], ah, bh[nt]);
                    MMA_BF16(acc[mt][nt], ah, bl[nt]);
                    MMA_BF16(acc[mt][nt], al, bh[nt]);
                }
            }
        }

        if (c < 15) storeA(buf^1, areg);   // same inter-sync window; visible after next sync
    }
    __syncthreads();

    // epilogue preloads
    if (EPI == 1) {
        if (tid < 256) sEpi[tid] = g_cbF[b*512 + n0 + tid];
    } else if (EPI == 2 || EPI == 3 || EPI == 5) {
        if (tid < 256) sEpi[tid] = bias[n0 + tid];
    } else if (EPI == 6) {
        if (tid < 256) {
            sEpi[tid]        = bias[n0 + tid];           // mix_b2
            sEpi[256 + tid]  = g_gam[b*512 + n0 + tid];
            sEpi[512 + tid]  = g_bet[b*512 + n0 + tid];
            sEpi[768 + tid]  = g_gate[b*512 + n0 + tid];
            sEpi[1024 + tid] = flng[n0 + tid];
            sEpi[1280 + tid] = flnb[n0 + tid];
        }
    }
    __syncthreads();

    #pragma unroll
    for (int mt = 0; mt < 4; mt++) {
        #pragma unroll
        for (int rh = 0; rh < 2; rh++) {
            int tok = tok0 + wm*64 + mt*16 + gid + rh*8;
            float muv = 0.f, rsv = 0.f, mskv = 0.f;
            if (EPI == 6) {
                muv = g_mu[tok]; rsv = g_rs[tok];
                mskv = (pm[tok] != 0u) ? 1.f : 0.f;
            }
            #pragma unroll
            for (int nt = 0; nt < 8; nt++) {
                #pragma unroll
                for (int rb = 0; rb < 2; rb++) {
                    int nl = wn*64 + nt*8 + tg*2 + rb;
                    float av = acc[mt][nt][rh*2 + rb];
                    if (EPI == 1) {
                        g_ucpre[(size_t)tok*512 + n0 + nl] = fmaxf(av + sEpi[nl], 0.f);
                    } else if (EPI == 2) {
                        g_q[(size_t)tok*512 + n0 + nl] = av + sEpi[nl];
                    } else if (EPI == 3) {
                        g_ao[(size_t)tok*512 + n0 + nl] = av + sEpi[nl];
                    } else if (EPI == 4) {
                        pOut[(size_t)tok*OSTR + n0 + nl] = av;
                    } else if (EPI == 7) {
                        pOut[(size_t)tok*OSTR + n0 + nl] += av;
                    } else if (EPI == 5) {
                        size_t gi = (size_t)tok*OSTR + n0 + nl;
                        float v = prev[gi] + av + sEpi[nl];
                        if (v != v) v = 1e20f;                 // NaN canary
                        else        v = fmaxf(v, 0.f);
                        pOut[gi] = v;
                    } else {  // EPI 6: final combine
                        size_t gi = (size_t)tok*512 + n0 + nl;
                        float ua = prev[gi] + av + sEpi[nl];
                        float xv = xp[gi];
                        float xh = (xv - muv)*rsv;
                        float base = sEpi[256 + nl]*fmaf(xh, sEpi[1024 + nl], sEpi[1280 + nl]) + sEpi[512 + nl];
                        g_pre[gi] = base + sEpi[768 + nl]*mskv*(g_ucn[gi] + ua);
                    }
                }
            }
        }
    }
}

// ===================== launch =====================
extern "C" void kernel_launch(void* const* d_in, const int* in_sizes, int n_in,
                              void* d_out, int out_size) {
    const float* x          = (const float*)d_in[0];
    const float* context    = (const float*)d_in[1];
    const unsigned int* mask = (const unsigned int*)d_in[2];
    const float* film_ln_g  = (const float*)d_in[3];
    const float* film_ln_b  = (const float*)d_in[4];
    const float* film_w     = (const float*)d_in[5];
    const float* film_b     = (const float*)d_in[6];
    const float* concat_w   = (const float*)d_in[7];
    const float* concat_b   = (const float*)d_in[8];
    const float* concat_ln_g= (const float*)d_in[9];
    const float* concat_ln_b= (const float*)d_in[10];
    const float* ctx_w1     = (const float*)d_in[11];
    const float* ctx_b1     = (const float*)d_in[12];
    const float* ctx_w2     = (const float*)d_in[13];
    const float* ctx_b2     = (const float*)d_in[14];
    const float* q_ln_g     = (const float*)d_in[15];
    const float* q_ln_b     = (const float*)d_in[16];
    const float* in_proj_w  = (const float*)d_in[17];
    const float* in_proj_b  = (const float*)d_in[18];
    const float* out_proj_w = (const float*)d_in[19];
    const float* out_proj_b = (const float*)d_in[20];
    const float* mix_w1     = (const float*)d_in[21];
    const float* mix_b1     = (const float*)d_in[22];
    const float* mix_w2     = (const float*)d_in[23];
    const float* mix_b2     = (const float*)d_in[24];
    const float* out_ln_g   = (const float*)d_in[25];
    const float* out_ln_b   = (const float*)d_in[26];
    const float* gate_w     = (const float*)d_in[27];
    const float* gate_b     = (const float*)d_in[28];
    float* out = (float*)d_out;

    float* t_ptr;  cudaGetSymbolAddress((void**)&t_ptr,  g_t);
    float* t2_ptr; cudaGetSymbolAddress((void**)&t2_ptr, g_t2);
    float* h_ptr;  cudaGetSymbolAddress((void**)&h_ptr,  g_h);
    float* xq_ptr; cudaGetSymbolAddress((void**)&xq_ptr, g_xq);
    float* a_ptr;  cudaGetSymbolAddress((void**)&a_ptr,  g_a);
    float* ao_ptr; cudaGetSymbolAddress((void**)&ao_ptr, g_ao);
    float* d_ptr;  cudaGetSymbolAddress((void**)&d_ptr,  g_d);
    float* p_ptr;  cudaGetSymbolAddress((void**)&p_ptr,  g_p);
    __nv_bfloat16 *wcxh, *wcxl, *wqh, *wql, *woh, *wol, *w1h, *w1l, *w2h, *w2l;
    cudaGetSymbolAddress((void**)&wcxh, g_wcxh); cudaGetSymbolAddress((void**)&wcxl, g_wcxl);
    cudaGetSymbolAddress((void**)&wqh,  g_wqh);  cudaGetSymbolAddress((void**)&wql,  g_wql);
    cudaGetSymbolAddress((void**)&woh,  g_woh);  cudaGetSymbolAddress((void**)&wol,  g_wol);
    cudaGetSymbolAddress((void**)&w1h,  g_w1h);  cudaGetSymbolAddress((void**)&w1l,  g_w1l);
    cudaGetSymbolAddress((void**)&w2h,  g_w2h);  cudaGetSymbolAddress((void**)&w2l,  g_w2l);

    #define SETSM(K) cudaFuncSetAttribute(K, cudaFuncAttributeMaxDynamicSharedMemorySize, GSMEM)
    SETSM((gemm_v12<1,512,512,512,0>));
    SETSM((gemm_v12<2,512,512,512,0>));
    SETSM((gemm_v12<3,512,512,512,0>));
    SETSM((gemm_v12<4,2048,512,1024,0>));   SETSM((gemm_v12<4,2048,512,1024,512>));
    SETSM((gemm_v12<7,2048,512,1024,0>));   SETSM((gemm_v12<7,2048,512,1024,512>));
    SETSM((gemm_v12<5,2048,512,1024,0>));   SETSM((gemm_v12<5,2048,512,1024,512>));
    SETSM((gemm_v12<4,1024,1024,512,0>));
    SETSM((gemm_v12<6,1024,1024,512,0>));

    // weight preprocessing (bf16 hi/lo)
    split_cwx_v12<<<(512*512)/256, 256>>>(concat_w);
    split_plain_v12<<<(512*512)/256, 256>>>(in_proj_w, wqh, wql, 512*512);    // first 512 rows = Wq
    split_plain_v12<<<(512*512)/256, 256>>>(out_proj_w, woh, wol, 512*512);
    split_plain_v12<<<(1024*2048)/256, 256>>>(mix_w1, w1h, w1l, 1024*2048);
    split_plain_v12<<<(512*1024)/256, 256>>>(mix_w2, w2h, w2l, 512*1024);

    ctx_kernel_v12<<<Bm, 256>>>(context, film_w, film_b, ctx_w1, ctx_b1, ctx_w2, ctx_b2,
                                in_proj_w, in_proj_b, gate_w, gate_b, concat_w, concat_b);
    prep_x_v12<<<MT/8, 256>>>(x, q_ln_g, q_ln_b);

    dim3 G(256, 2);
    // G1: ucpre = relu(x @ Wcx^T + cbF)
    gemm_v12<1,512,512,512,0><<<G, 256, GSMEM>>>(x, wcxh, wcxl, nullptr, nullptr, nullptr, nullptr, nullptr, nullptr, nullptr);
    ln_kernel_v12<0><<<MT/8, 256>>>(concat_ln_g, concat_ln_b, nullptr);
    // G2: q
    gemm_v12<2,512,512,512,0><<<G, 256, GSMEM>>>(xq_ptr, wqh, wql, in_proj_b, nullptr, nullptr, nullptr, nullptr, nullptr, nullptr);
    attn_kernel_v12<<<MT/4, 256>>>();
    // G3: ao
    gemm_v12<3,512,512,512,0><<<G, 256, GSMEM>>>(a_ptr, woh, wol, out_proj_b, nullptr, nullptr, nullptr, nullptr, nullptr, nullptr);
    dp_kernel_v12<<<(MT*512)/256, 256>>>(x);

    // G4: h = relu(sum_s A_s @ W1_s^T + mb1), 4 K-slices x 2 N-halves (all K=512)
    const float* Asrc[4] = { x, ao_ptr, d_ptr, p_ptr };
    for (int s = 0; s < 4; s++) {
        const float* As = Asrc[s];
        const __nv_bfloat16* Bh = w1h + s*512;
        const __nv_bfloat16* Bl = w1l + s*512;
        if (s == 0) {
            gemm_v12<4,2048,512,1024,0>  <<<G, 256, GSMEM>>>(As, Bh, Bl, nullptr, t_ptr, nullptr, nullptr, nullptr, nullptr, nullptr);
            gemm_v12<4,2048,512,1024,512><<<G, 256, GSMEM>>>(As, Bh, Bl, nullptr, t_ptr, nullptr, nullptr, nullptr, nullptr, nullptr);
        } else if (s < 3) {
            gemm_v12<7,2048,512,1024,0>  <<<G, 256, GSMEM>>>(As, Bh, Bl, nullptr, t_ptr, nullptr, nullptr, nullptr, nullptr, nullptr);
            gemm_v12<7,2048,512,1024,512><<<G, 256, GSMEM>>>(As, Bh, Bl, nullptr, t_ptr, nullptr, nullptr, nullptr, nullptr, nullptr);
        } else {
            gemm_v12<5,2048,512,1024,0>  <<<G, 256, GSMEM>>>(As, Bh, Bl, mix_b1, h_ptr, t_ptr, nullptr, nullptr, nullptr, nullptr);
            gemm_v12<5,2048,512,1024,512><<<G, 256, GSMEM>>>(As, Bh, Bl, mix_b1, h_ptr, t_ptr, nullptr, nullptr, nullptr, nullptr);
        }
    }
    // G5: 2 K-slices; slice1 carries final combine
    gemm_v12<4,1024,1024,512,0><<<G, 256, GSMEM>>>(h_ptr, w2h, w2l, nullptr, t2_ptr, nullptr, nullptr, nullptr, nullptr, nullptr);
    gemm_v12<6,1024,1024,512,0><<<G, 256, GSMEM>>>(h_ptr + 512, w2h + 512, w2l + 512, mix_b2, nullptr, t2_ptr, x, mask, film_ln_g, film_ln_b);
    ln_kernel_v12<1><<<MT/8, 256>>>(out_ln_g, out_ln_b, out);
}

// round 14
// speedup vs baseline: 3.6450x; 1.3946x over previous
#include <cuda_runtime.h>
#include <cuda_fp16.h>
#include <cstdint>
#include <math.h>

#define MT 32768
#define Cm 256
#define Bm 8

// ===================== helpers =====================
__device__ __forceinline__ uint32_t smem_u32(const void* p) {
    uint32_t a;
    asm("{ .reg .u64 t; cvta.to.shared.u64 t, %1; cvt.u32.u64 %0, t; }" : "=r"(a) : "l"(p));
    return a;
}
__device__ __forceinline__ void cpa16(uint32_t s, const void* g) {
    asm volatile("cp.async.cg.shared.global [%0], [%1], 16;" :: "r"(s), "l"(g));
}
#define CP_COMMIT() asm volatile("cp.async.commit_group;" ::: "memory")
#define CP_WAIT0()  asm volatile("cp.async.wait_group 0;" ::: "memory")

#define MMA_F16(C, A, B) asm volatile( \
    "mma.sync.aligned.m16n8k16.row.col.f32.f16.f16.f32 " \
    "{%0,%1,%2,%3}, {%4,%5,%6,%7}, {%8,%9}, {%0,%1,%2,%3};" \
    : "+f"((C)[0]), "+f"((C)[1]), "+f"((C)[2]), "+f"((C)[3]) \
    : "r"((A)[0]), "r"((A)[1]), "r"((A)[2]), "r"((A)[3]), "r"((B)[0]), "r"((B)[1]))

__device__ __forceinline__ uint32_t pkh(float a, float b) {
    __half2 t = __floats2half2_rn(a, b);   // a = lower k col
    return reinterpret_cast<uint32_t&>(t);
}

// ===================== device global scratch =====================
__device__ float g_xq[MT*512];
__device__ float g_q[MT*512];
__device__ float g_a[MT*512];
__device__ float g_ao[MT*512];
__device__ float g_d[MT*512];    // x - ao
__device__ float g_p[MT*512];    // x * ao
__device__ float g_h[MT*1024];
__device__ float g_t[MT*1024];   // G4 partial accumulator
__device__ float g_t2[MT*512];   // G5 partial accumulator
__device__ float g_ucpre[MT*512], g_ucn[MT*512], g_pre[MT*512];
__device__ float g_mu[MT], g_rs[MT];
__device__ float g_cbF[Bm*512], g_gam[Bm*512], g_bet[Bm*512], g_gate[Bm*512];
__device__ float g_Kc[Bm*2*512], g_Vc[Bm*2*512];
// preprocessed fp16 weights
__device__ __half g_wcx[512*512];
__device__ __half g_wq[512*512];
__device__ __half g_wo[512*512];
__device__ __half g_w1[1024*2048];
__device__ __half g_w2[512*1024];

// ===================== weight preprocessing =====================
__global__ void cvt_plain_v13(const float* __restrict__ src, __half* dst, int n) {
    int i = blockIdx.x*blockDim.x + threadIdx.x;
    if (i >= n) return;
    dst[i] = __float2half_rn(src[i]);
}
__global__ void cvt_cwx_v13(const float* __restrict__ cw) {  // concat_w x-part [512][768] -> [512][512]
    int i = blockIdx.x*blockDim.x + threadIdx.x;
    if (i >= 512*512) return;
    int r = i >> 9, c = i & 511;
    g_wcx[i] = __float2half_rn(cw[r*768 + c]);
}

// ===================== per-batch context pipeline (R2-validated) =====================
__global__ void ctx_kernel_v13(const float* __restrict__ ctx,
    const float* __restrict__ film_w, const float* __restrict__ film_b,
    const float* __restrict__ w1, const float* __restrict__ b1,
    const float* __restrict__ w2, const float* __restrict__ b2,
    const float* __restrict__ inw, const float* __restrict__ inb,
    const float* __restrict__ gw, const float* __restrict__ gb,
    const float* __restrict__ cw, const float* __restrict__ cb)
{
    __shared__ float sc[Cm];
    __shared__ float sh[512];
    __shared__ float st[1024];
    int b = blockIdx.x, tid = threadIdx.x;
    if (tid < Cm) sc[tid] = ctx[b*Cm + tid];
    __syncthreads();
    for (int j = tid; j < 1024; j += 256) {
        const float* w = film_w + (size_t)j*Cm;
        float s = film_b[j];
        #pragma unroll 4
        for (int c = 0; c < Cm; c++) s = fmaf(w[c], sc[c], s);
        if (j < 512) g_gam[b*512 + j] = 1.f + s;
        else         g_bet[b*512 + (j-512)] = s;
    }
    for (int d = tid; d < 512; d += 256) {
        const float* w = gw + (size_t)d*Cm;
        float s = gb[d];
        #pragma unroll 4
        for (int c = 0; c < Cm; c++) s = fmaf(w[c], sc[c], s);
        g_gate[b*512 + d] = 1.f/(1.f + expf(-s));
    }
    for (int n = tid; n < 512; n += 256) {
        const float* w = cw + (size_t)n*768 + 512;
        float s = cb[n];
        #pragma unroll 4
        for (int c = 0; c < Cm; c++) s = fmaf(w[c], sc[c], s);
        g_cbF[b*512 + n] = s;
    }
    for (int i = tid; i < 512; i += 256) {
        const float* w = w1 + (size_t)i*Cm;
        float s = b1[i];
        #pragma unroll 4
        for (int c = 0; c < Cm; c++) s = fmaf(w[c], sc[c], s);
        sh[i] = 0.5f*s*(1.f + erff(s*0.70710678118654752f));
    }
    __syncthreads();
    for (int m = tid; m < 1024; m += 256) {
        const float* w = w2 + (size_t)m*512;
        float s = b2[m];
        #pragma unroll 4
        for (int e = 0; e < 512; e++) s = fmaf(w[e], sh[e], s);
        st[m] = s;
    }
    __syncthreads();
    for (int d = tid; d < 512; d += 256) {
        const float* wk = inw + (size_t)(512 + d)*512;
        const float* wv = inw + (size_t)(1024 + d)*512;
        float k0 = inb[512 + d], k1 = k0;
        float v0 = inb[1024 + d], v1 = v0;
        #pragma unroll 4
        for (int e = 0; e < 512; e++) {
            float a = wk[e], c = wv[e];
            k0 = fmaf(a, st[e],     k0);
            k1 = fmaf(a, st[512+e], k1);
            v0 = fmaf(c, st[e],     v0);
            v1 = fmaf(c, st[512+e], v1);
        }
        g_Kc[(b*2+0)*512 + d] = k0; g_Kc[(b*2+1)*512 + d] = k1;
        g_Vc[(b*2+0)*512 + d] = v0; g_Vc[(b*2+1)*512 + d] = v1;
    }
}

// ===================== prologue: LN stats + x_q =====================
__global__ void prep_x_v13(const float* __restrict__ x,
                           const float* __restrict__ qg, const float* __restrict__ qb)
{
    int tok = blockIdx.x*8 + (threadIdx.x >> 5);
    int lane = threadIdx.x & 31;
    const float* row = x + (size_t)tok*512;
    float v[16];
    float s = 0.f, s2 = 0.f;
    #pragma unroll
    for (int i = 0; i < 16; i++) { v[i] = row[lane + i*32]; s += v[i]; s2 = fmaf(v[i], v[i], s2); }
    #pragma unroll
    for (int o = 16; o; o >>= 1) {
        s  += __shfl_xor_sync(0xffffffffu, s,  o);
        s2 += __shfl_xor_sync(0xffffffffu, s2, o);
    }
    float m = s*(1.f/512.f);
    float r = rsqrtf(s2*(1.f/512.f) - m*m + 1e-5f);
    if (lane == 0) { g_mu[tok] = m; g_rs[tok] = r; }
    #pragma unroll
    for (int i = 0; i < 16; i++) {
        int k = lane + i*32;
        g_xq[(size_t)tok*512 + k] = (v[i] - m)*r*qg[k] + qb[k];
    }
}

// ===================== standalone attention (R2-validated) =====================
__global__ void attn_kernel_v13()
{
    int wid = threadIdx.x >> 5, lane = threadIdx.x & 31;
    int tok = blockIdx.x*4 + (wid >> 1);
    int h   = wid & 1;
    int b   = tok >> 12;
    const float* qrow = g_q + (size_t)tok*512 + h*256;
    const float* K0 = g_Kc + (size_t)(b*2+0)*512 + h*256;
    const float* K1 = g_Kc + (size_t)(b*2+1)*512 + h*256;
    float s0 = 0.f, s1 = 0.f;
    for (int d = lane; d < 256; d += 32) {
        float qv = qrow[d];
        s0 = fmaf(qv, K0[d], s0);
        s1 = fmaf(qv, K1[d], s1);
    }
    #pragma unroll
    for (int o = 16; o; o >>= 1) {
        s0 += __shfl_xor_sync(0xffffffffu, s0, o);
        s1 += __shfl_xor_sync(0xffffffffu, s1, o);
    }
    s0 *= 0.0625f; s1 *= 0.0625f;
    float mx = fmaxf(s0, s1);
    float e0 = expf(s0 - mx), e1 = expf(s1 - mx);
    float inv = 1.f/(e0 + e1);
    float p0 = e0*inv, p1 = e1*inv;
    const float* V0 = g_Vc + (size_t)(b*2+0)*512 + h*256;
    const float* V1 = g_Vc + (size_t)(b*2+1)*512 + h*256;
    for (int d = lane; d < 256; d += 32)
        g_a[(size_t)tok*512 + h*256 + d] = p0*V0[d] + p1*V1[d];
}

// ===================== elementwise: d = x - ao, p = x*ao =====================
__global__ void dp_kernel_v13(const float* __restrict__ x)
{
    size_t i = (size_t)blockIdx.x*256 + threadIdx.x;
    float xv = x[i], av = g_ao[i];
    g_d[i] = xv - av;
    g_p[i] = xv * av;
}

// ===================== LN kernels =====================
template<int W>
__global__ void ln_kernel_v13(const float* __restrict__ gv, const float* __restrict__ bv, float* __restrict__ outp)
{
    int tok = blockIdx.x*8 + (threadIdx.x >> 5);
    int lane = threadIdx.x & 31;
    const float* in = (W == 0) ? g_ucpre : g_pre;
    float* out = (W == 0) ? g_ucn : outp;
    const float* row = in + (size_t)tok*512;
    float v[16];
    float s = 0.f, s2 = 0.f;
    #pragma unroll
    for (int i = 0; i < 16; i++) { v[i] = row[lane + i*32]; s += v[i]; s2 = fmaf(v[i], v[i], s2); }
    #pragma unroll
    for (int o = 16; o; o >>= 1) {
        s  += __shfl_xor_sync(0xffffffffu, s,  o);
        s2 += __shfl_xor_sync(0xffffffffu, s2, o);
    }
    float m = s*(1.f/512.f);
    float r = rsqrtf(s2*(1.f/512.f) - m*m + 1e-5f);
    #pragma unroll
    for (int i = 0; i < 16; i++) {
        int k = lane + i*32;
        out[(size_t)tok*512 + k] = (v[i] - m)*r*gv[k] + bv[k];
    }
}

// ===================== pipelined warp-MMA GEMM slice: fp16 single pass, K=512, chunk=32, double-buffered =====================
// Row = 32 halves (64B) + 16B pad = 80B.
#define RB2     80
#define APL     (128*RB2)
#define BPL     (256*RB2)
#define OFF_A   0
#define OFF_B   (2*APL)
#define OFF_EPI (OFF_B + 2*BPL)
#define GSMEM   (OFF_EPI + 1536*4 + 256)

// EPI: 1=UC 2=Q 3=AO 4=WRITE 7=ADD 5=HRELU(prev+acc+bias, canary) 6=FINAL
template<int EPI, int BSTR, int AROW, int OSTR, int NOFF>
__global__ void __launch_bounds__(256, 1)
gemm_v13(const float* __restrict__ pA, const __half* __restrict__ pB,
         const float* __restrict__ bias, float* __restrict__ pOut,
         const float* __restrict__ prev, const float* __restrict__ xp,
         const unsigned int* __restrict__ pm,
         const float* __restrict__ flng, const float* __restrict__ flnb)
{
    extern __shared__ char smem[];
    uint32_t sb = smem_u32(smem);
    float* sEpi = (float*)(smem + OFF_EPI);

    const int tid = threadIdx.x;
    const int wid = tid >> 5, lane = tid & 31;
    const int gid = lane >> 2, tg = lane & 3;
    const int wm = wid >> 2, wn = wid & 3;
    const int tok0 = blockIdx.x * 128;
    const int n0   = NOFF + blockIdx.y * 256;
    const int b    = tok0 >> 12;

    const int ar0 = tid >> 3, aq0 = tid & 7;   // A: rows ar0+it*32, float4 index aq0

    float acc[4][8][4];
    #pragma unroll
    for (int mt = 0; mt < 4; mt++)
        #pragma unroll
        for (int nt = 0; nt < 8; nt++)
            #pragma unroll
            for (int r = 0; r < 4; r++) acc[mt][nt][r] = 0.f;

    auto issueB = [&](int c, int buf) {
        const int kb = c*32;
        #pragma unroll
        for (int it = 0; it < 4; it++) {
            int u = tid + it*256;
            int r = u >> 2, q = u & 3;
            cpa16(sb + OFF_B + (uint32_t)(buf*BPL + r*RB2 + q*16),
                  pB + (size_t)(n0 + r)*BSTR + kb + q*8);
        }
        CP_COMMIT();
    };
    auto loadA = [&](int c, float4* areg) {
        const int kb = c*32;
        #pragma unroll
        for (int it = 0; it < 4; it++)
            areg[it] = *(const float4*)(pA + (size_t)(tok0 + ar0 + it*32)*AROW + kb + aq0*4);
    };
    auto storeA = [&](int buf, const float4* areg) {
        #pragma unroll
        for (int it = 0; it < 4; it++) {
            float4 va = areg[it];
            uint32_t off = (uint32_t)(buf*APL + (ar0 + it*32)*RB2 + aq0*8);
            *(uint2*)(smem + OFF_A + off) = make_uint2(pkh(va.x, va.y), pkh(va.z, va.w));
        }
    };

    // prologue: chunk 0 into buf 0
    {
        float4 areg[4];
        loadA(0, areg);
        issueB(0, 0);
        storeA(0, areg);
    }

    for (int c = 0; c < 16; c++) {
        const int buf = c & 1;
        CP_WAIT0();
        __syncthreads();

        float4 areg[4];
        if (c < 15) {
            issueB(c+1, buf^1);
            loadA(c+1, areg);
        }

        #pragma unroll
        for (int ks = 0; ks < 32; ks += 16) {
            uint32_t bh[8][2];
            #pragma unroll
            for (int nt = 0; nt < 8; nt++) {
                uint32_t o0 = OFF_B + (uint32_t)(buf*BPL + (wn*64 + nt*8 + gid)*RB2 + (ks + tg*2)*2);
                bh[nt][0] = *(const uint32_t*)(smem + o0);
                bh[nt][1] = *(const uint32_t*)(smem + o0 + 16);
            }
            #pragma unroll
            for (int mt = 0; mt < 4; mt++) {
                uint32_t oh = OFF_A + (uint32_t)(buf*APL + (wm*64 + mt*16 + gid)*RB2 + (ks + tg*2)*2);
                uint32_t ah[4];
                ah[0] = *(const uint32_t*)(smem + oh);
                ah[1] = *(const uint32_t*)(smem + oh + 8*RB2);
                ah[2] = *(const uint32_t*)(smem + oh + 16);
                ah[3] = *(const uint32_t*)(smem + oh + 8*RB2 + 16);
                #pragma unroll
                for (int nt = 0; nt < 8; nt++)
                    MMA_F16(acc[mt][nt], ah, bh[nt]);
            }
        }

        if (c < 15) storeA(buf^1, areg);
    }
    __syncthreads();

    // epilogue preloads
    if (EPI == 1) {
        if (tid < 256) sEpi[tid] = g_cbF[b*512 + n0 + tid];
    } else if (EPI == 2 || EPI == 3 || EPI == 5) {
        if (tid < 256) sEpi[tid] = bias[n0 + tid];
    } else if (EPI == 6) {
        if (tid < 256) {
            sEpi[tid]        = bias[n0 + tid];           // mix_b2
            sEpi[256 + tid]  = g_gam[b*512 + n0 + tid];
            sEpi[512 + tid]  = g_bet[b*512 + n0 + tid];
            sEpi[768 + tid]  = g_gate[b*512 + n0 + tid];
            sEpi[1024 + tid] = flng[n0 + tid];
            sEpi[1280 + tid] = flnb[n0 + tid];
        }
    }
    __syncthreads();

    #pragma unroll
    for (int mt = 0; mt < 4; mt++) {
        #pragma unroll
        for (int rh = 0; rh < 2; rh++) {
            int tok = tok0 + wm*64 + mt*16 + gid + rh*8;
            float muv = 0.f, rsv = 0.f, mskv = 0.f;
            if (EPI == 6) {
                muv = g_mu[tok]; rsv = g_rs[tok];
                mskv = (pm[tok] != 0u) ? 1.f : 0.f;
            }
            #pragma unroll
            for (int nt = 0; nt < 8; nt++) {
                #pragma unroll
                for (int rb = 0; rb < 2; rb++) {
                    int nl = wn*64 + nt*8 + tg*2 + rb;
                    float av = acc[mt][nt][rh*2 + rb];
                    if (EPI == 1) {
                        g_ucpre[(size_t)tok*512 + n0 + nl] = fmaxf(av + sEpi[nl], 0.f);
                    } else if (EPI == 2) {
                        g_q[(size_t)tok*512 + n0 + nl] = av + sEpi[nl];
                    } else if (EPI == 3) {
                        g_ao[(size_t)tok*512 + n0 + nl] = av + sEpi[nl];
                    } else if (EPI == 4) {
                        pOut[(size_t)tok*OSTR + n0 + nl] = av;
                    } else if (EPI == 7) {
                        pOut[(size_t)tok*OSTR + n0 + nl] += av;
                    } else if (EPI == 5) {
                        size_t gi = (size_t)tok*OSTR + n0 + nl;
                        float v = prev[gi] + av + sEpi[nl];
                        if (v != v) v = 1e20f;                 // NaN canary
                        else        v = fmaxf(v, 0.f);
                        pOut[gi] = v;
                    } else {  // EPI 6: final combine
                        size_t gi = (size_t)tok*512 + n0 + nl;
                        float ua = prev[gi] + av + sEpi[nl];
                        float xv = xp[gi];
                        float xh = (xv - muv)*rsv;
                        float base = sEpi[256 + nl]*fmaf(xh, sEpi[1024 + nl], sEpi[1280 + nl]) + sEpi[512 + nl];
                        g_pre[gi] = base + sEpi[768 + nl]*mskv*(g_ucn[gi] + ua);
                    }
                }
            }
        }
    }
}

// ===================== launch =====================
extern "C" void kernel_launch(void* const* d_in, const int* in_sizes, int n_in,
                              void* d_out, int out_size) {
    const float* x          = (const float*)d_in[0];
    const float* context    = (const float*)d_in[1];
    const unsigned int* mask = (const unsigned int*)d_in[2];
    const float* film_ln_g  = (const float*)d_in[3];
    const float* film_ln_b  = (const float*)d_in[4];
    const float* film_w     = (const float*)d_in[5];
    const float* film_b     = (const float*)d_in[6];
    const float* concat_w   = (const float*)d_in[7];
    const float* concat_b   = (const float*)d_in[8];
    const float* concat_ln_g= (const float*)d_in[9];
    const float* concat_ln_b= (const float*)d_in[10];
    const float* ctx_w1     = (const float*)d_in[11];
    const float* ctx_b1     = (const float*)d_in[12];
    const float* ctx_w2     = (const float*)d_in[13];
    const float* ctx_b2     = (const float*)d_in[14];
    const float* q_ln_g     = (const float*)d_in[15];
    const float* q_ln_b     = (const float*)d_in[16];
    const float* in_proj_w  = (const float*)d_in[17];
    const float* in_proj_b  = (const float*)d_in[18];
    const float* out_proj_w = (const float*)d_in[19];
    const float* out_proj_b = (const float*)d_in[20];
    const float* mix_w1     = (const float*)d_in[21];
    const float* mix_b1     = (const float*)d_in[22];
    const float* mix_w2     = (const float*)d_in[23];
    const float* mix_b2     = (const float*)d_in[24];
    const float* out_ln_g   = (const float*)d_in[25];
    const float* out_ln_b   = (const float*)d_in[26];
    const float* gate_w     = (const float*)d_in[27];
    const float* gate_b     = (const float*)d_in[28];
    float* out = (float*)d_out;

    float* t_ptr;  cudaGetSymbolAddress((void**)&t_ptr,  g_t);
    float* t2_ptr; cudaGetSymbolAddress((void**)&t2_ptr, g_t2);
    float* h_ptr;  cudaGetSymbolAddress((void**)&h_ptr,  g_h);
    float* xq_ptr; cudaGetSymbolAddress((void**)&xq_ptr, g_xq);
    float* a_ptr;  cudaGetSymbolAddress((void**)&a_ptr,  g_a);
    float* ao_ptr; cudaGetSymbolAddress((void**)&ao_ptr, g_ao);
    float* d_ptr;  cudaGetSymbolAddress((void**)&d_ptr,  g_d);
    float* p_ptr;  cudaGetSymbolAddress((void**)&p_ptr,  g_p);
    __half *wcx, *wq, *wo, *w1, *w2;
    cudaGetSymbolAddress((void**)&wcx, g_wcx);
    cudaGetSymbolAddress((void**)&wq,  g_wq);
    cudaGetSymbolAddress((void**)&wo,  g_wo);
    cudaGetSymbolAddress((void**)&w1,  g_w1);
    cudaGetSymbolAddress((void**)&w2,  g_w2);

    #define SETSM(K) cudaFuncSetAttribute(K, cudaFuncAttributeMaxDynamicSharedMemorySize, GSMEM)
    SETSM((gemm_v13<1,512,512,512,0>));
    SETSM((gemm_v13<2,512,512,512,0>));
    SETSM((gemm_v13<3,512,512,512,0>));
    SETSM((gemm_v13<4,2048,512,1024,0>));   SETSM((gemm_v13<4,2048,512,1024,512>));
    SETSM((gemm_v13<7,2048,512,1024,0>));   SETSM((gemm_v13<7,2048,512,1024,512>));
    SETSM((gemm_v13<5,2048,512,1024,0>));   SETSM((gemm_v13<5,2048,512,1024,512>));
    SETSM((gemm_v13<4,1024,1024,512,0>));
    SETSM((gemm_v13<6,1024,1024,512,0>));

    // weight preprocessing (fp16)
    cvt_cwx_v13<<<(512*512)/256, 256>>>(concat_w);
    cvt_plain_v13<<<(512*512)/256, 256>>>(in_proj_w, wq, 512*512);    // rows 0..511 = Wq
    cvt_plain_v13<<<(512*512)/256, 256>>>(out_proj_w, wo, 512*512);
    cvt_plain_v13<<<(1024*2048)/256, 256>>>(mix_w1, w1, 1024*2048);
    cvt_plain_v13<<<(512*1024)/256, 256>>>(mix_w2, w2, 512*1024);

    ctx_kernel_v13<<<Bm, 256>>>(context, film_w, film_b, ctx_w1, ctx_b1, ctx_w2, ctx_b2,
                                in_proj_w, in_proj_b, gate_w, gate_b, concat_w, concat_b);
    prep_x_v13<<<MT/8, 256>>>(x, q_ln_g, q_ln_b);

    dim3 G(256, 2);
    // G1: ucpre = relu(x @ Wcx^T + cbF)
    gemm_v13<1,512,512,512,0><<<G, 256, GSMEM>>>(x, wcx, nullptr, nullptr, nullptr, nullptr, nullptr, nullptr, nullptr);
    ln_kernel_v13<0><<<MT/8, 256>>>(concat_ln_g, concat_ln_b, nullptr);
    // G2: q
    gemm_v13<2,512,512,512,0><<<G, 256, GSMEM>>>(xq_ptr, wq, in_proj_b, nullptr, nullptr, nullptr, nullptr, nullptr, nullptr);
    attn_kernel_v13<<<MT/4, 256>>>();
    // G3: ao
    gemm_v13<3,512,512,512,0><<<G, 256, GSMEM>>>(a_ptr, wo, out_proj_b, nullptr, nullptr, nullptr, nullptr, nullptr, nullptr);
    dp_kernel_v13<<<(MT*512)/256, 256>>>(x);

    // G4: h = relu(sum_s A_s @ W1_s^T + mb1), 4 K-slices x 2 N-halves (all K=512)
    const float* Asrc[4] = { x, ao_ptr, d_ptr, p_ptr };
    for (int s = 0; s < 4; s++) {
        const float* As = Asrc[s];
        const __half* Bs = w1 + s*512;
        if (s == 0) {
            gemm_v13<4,2048,512,1024,0>  <<<G, 256, GSMEM>>>(As, Bs, nullptr, t_ptr, nullptr, nullptr, nullptr, nullptr, nullptr);
            gemm_v13<4,2048,512,1024,512><<<G, 256, GSMEM>>>(As, Bs, nullptr, t_ptr, nullptr, nullptr, nullptr, nullptr, nullptr);
        } else if (s < 3) {
            gemm_v13<7,2048,512,1024,0>  <<<G, 256, GSMEM>>>(As, Bs, nullptr, t_ptr, nullptr, nullptr, nullptr, nullptr, nullptr);
            gemm_v13<7,2048,512,1024,512><<<G, 256, GSMEM>>>(As, Bs, nullptr, t_ptr, nullptr, nullptr, nullptr, nullptr, nullptr);
        } else {
            gemm_v13<5,2048,512,1024,0>  <<<G, 256, GSMEM>>>(As, Bs, mix_b1, h_ptr, t_ptr, nullptr, nullptr, nullptr, nullptr);
            gemm_v13<5,2048,512,1024,512><<<G, 256, GSMEM>>>(As, Bs, mix_b1, h_ptr, t_ptr, nullptr, nullptr, nullptr, nullptr);
        }
    }
    // G5: 2 K-slices; slice1 carries final combine
    gemm_v13<4,1024,1024,512,0><<<G, 256, GSMEM>>>(h_ptr, w2, nullptr, t2_ptr, nullptr, nullptr, nullptr, nullptr, nullptr);
    gemm_v13<6,1024,1024,512,0><<<G, 256, GSMEM>>>(h_ptr + 512, w2 + 512, mix_b2, nullptr, t2_ptr, x, mask, film_ln_g, film_ln_b);
    ln_kernel_v13<1><<<MT/8, 256>>>(out_ln_g, out_ln_b, out);
}

// round 16
// speedup vs baseline: 4.4649x; 1.2249x over previous
#include <cuda_runtime.h>
#include <cuda_fp16.h>
#include <cstdint>
#include <math.h>

#define MT 32768
#define Cm 256
#define Bm 8

// ===================== helpers =====================
__device__ __forceinline__ uint32_t smem_u32(const void* p) {
    uint32_t a;
    asm("{ .reg .u64 t; cvta.to.shared.u64 t, %1; cvt.u32.u64 %0, t; }" : "=r"(a) : "l"(p));
    return a;
}
__device__ __forceinline__ void cpa16(uint32_t s, const void* g) {
    asm volatile("cp.async.cg.shared.global [%0], [%1], 16;" :: "r"(s), "l"(g));
}
#define CP_COMMIT() asm volatile("cp.async.commit_group;" ::: "memory")
#define CP_WAIT0()  asm volatile("cp.async.wait_group 0;" ::: "memory")

#define MMA_F16(C, A, B) asm volatile( \
    "mma.sync.aligned.m16n8k16.row.col.f32.f16.f16.f32 " \
    "{%0,%1,%2,%3}, {%4,%5,%6,%7}, {%8,%9}, {%0,%1,%2,%3};" \
    : "+f"((C)[0]), "+f"((C)[1]), "+f"((C)[2]), "+f"((C)[3]) \
    : "r"((A)[0]), "r"((A)[1]), "r"((A)[2]), "r"((A)[3]), "r"((B)[0]), "r"((B)[1]))

__device__ __forceinline__ uint32_t pkh(float a, float b) {
    __half2 t = __floats2half2_rn(a, b);   // a = lower k col
    return reinterpret_cast<uint32_t&>(t);
}

// ===================== device global scratch =====================
__device__ float g_xq[MT*512];
__device__ float g_q[MT*512];
__device__ float g_a[MT*512];
__device__ float g_ao[MT*512];
__device__ float g_p[MT*512];    // x * ao
__device__ float g_h[MT*1024];
__device__ float g_t[MT*1024];   // G4 partial accumulator
__device__ float g_t2[MT*512];   // G5 partial accumulator
__device__ float g_ucpre[MT*512], g_ucn[MT*512], g_pre[MT*512];
__device__ float g_mu[MT], g_rs[MT];
__device__ float g_cbF[Bm*512], g_gam[Bm*512], g_bet[Bm*512], g_gate[Bm*512];
__device__ float g_Kc[Bm*2*512], g_Vc[Bm*2*512];
// preprocessed fp16 weights
__device__ __half g_wcx[512*512];
__device__ __half g_wq[512*512];
__device__ __half g_wo[512*512];
__device__ __half g_w1f[1024*1536];   // folded mix_w1: [Wa+Wc | Wb-Wc | Wd]
__device__ __half g_w2[512*1024];

// ===================== weight preprocessing =====================
__global__ void cvt_plain_v15(const float* __restrict__ src, __half* dst, int n) {
    int i = blockIdx.x*blockDim.x + threadIdx.x;
    if (i >= n) return;
    dst[i] = __float2half_rn(src[i]);
}
__global__ void cvt_cwx_v15(const float* __restrict__ cw) {  // concat_w x-part [512][768] -> [512][512]
    int i = blockIdx.x*blockDim.x + threadIdx.x;
    if (i >= 512*512) return;
    int r = i >> 9, c = i & 511;
    g_wcx[i] = __float2half_rn(cw[r*768 + c]);
}
__global__ void fold_w1_v15(const float* __restrict__ w1) {  // fp32 fold -> fp16
    int i = blockIdx.x*blockDim.x + threadIdx.x;
    if (i >= 1024*1536) return;
    int j = i / 1536, k = i - j*1536;
    const float* row = w1 + (size_t)j*2048;
    float v;
    if (k < 512)       v = row[k] + row[1024+k];      // Wa + Wc   (coeff of x)
    else if (k < 1024) v = row[k] - row[512+k];       // Wb - Wc   (coeff of ao)
    else               v = row[512+k];                // Wd        (coeff of x*ao)
    g_w1f[i] = __float2half_rn(v);
}

// ===================== per-batch context pipeline (R2-validated) =====================
__global__ void ctx_kernel_v15(const float* __restrict__ ctx,
    const float* __restrict__ film_w, const float* __restrict__ film_b,
    const float* __restrict__ w1, const float* __restrict__ b1,
    const float* __restrict__ w2, const float* __restrict__ b2,
    const float* __restrict__ inw, const float* __restrict__ inb,
    const float* __restrict__ gw, const float* __restrict__ gb,
    const float* __restrict__ cw, const float* __restrict__ cb)
{
    __shared__ float sc[Cm];
    __shared__ float sh[512];
    __shared__ float st[1024];
    int b = blockIdx.x, tid = threadIdx.x;
    if (tid < Cm) sc[tid] = ctx[b*Cm + tid];
    __syncthreads();
    for (int j = tid; j < 1024; j += 256) {
        const float* w = film_w + (size_t)j*Cm;
        float s = film_b[j];
        #pragma unroll 4
        for (int c = 0; c < Cm; c++) s = fmaf(w[c], sc[c], s);
        if (j < 512) g_gam[b*512 + j] = 1.f + s;
        else         g_bet[b*512 + (j-512)] = s;
    }
    for (int d = tid; d < 512; d += 256) {
        const float* w = gw + (size_t)d*Cm;
        float s = gb[d];
        #pragma unroll 4
        for (int c = 0; c < Cm; c++) s = fmaf(w[c], sc[c], s);
        g_gate[b*512 + d] = 1.f/(1.f + expf(-s));
    }
    for (int n = tid; n < 512; n += 256) {
        const float* w = cw + (size_t)n*768 + 512;
        float s = cb[n];
        #pragma unroll 4
        for (int c = 0; c < Cm; c++) s = fmaf(w[c], sc[c], s);
        g_cbF[b*512 + n] = s;
    }
    for (int i = tid; i < 512; i += 256) {
        const float* w = w1 + (size_t)i*Cm;
        float s = b1[i];
        #pragma unroll 4
        for (int c = 0; c < Cm; c++) s = fmaf(w[c], sc[c], s);
        sh[i] = 0.5f*s*(1.f + erff(s*0.70710678118654752f));
    }
    __syncthreads();
    for (int m = tid; m < 1024; m += 256) {
        const float* w = w2 + (size_t)m*512;
        float s = b2[m];
        #pragma unroll 4
        for (int e = 0; e < 512; e++) s = fmaf(w[e], sh[e], s);
        st[m] = s;
    }
    __syncthreads();
    for (int d = tid; d < 512; d += 256) {
        const float* wk = inw + (size_t)(512 + d)*512;
        const float* wv = inw + (size_t)(1024 + d)*512;
        float k0 = inb[512 + d], k1 = k0;
        float v0 = inb[1024 + d], v1 = v0;
        #pragma unroll 4
        for (int e = 0; e < 512; e++) {
            float a = wk[e], c = wv[e];
            k0 = fmaf(a, st[e],     k0);
            k1 = fmaf(a, st[512+e], k1);
            v0 = fmaf(c, st[e],     v0);
            v1 = fmaf(c, st[512+e], v1);
        }
        g_Kc[(b*2+0)*512 + d] = k0; g_Kc[(b*2+1)*512 + d] = k1;
        g_Vc[(b*2+0)*512 + d] = v0; g_Vc[(b*2+1)*512 + d] = v1;
    }
}

// ===================== prologue: LN stats + x_q =====================
__global__ void prep_x_v15(const float* __restrict__ x,
                           const float* __restrict__ qg, const float* __restrict__ qb)
{
    int tok = blockIdx.x*8 + (threadIdx.x >> 5);
    int lane = threadIdx.x & 31;
    const float* row = x + (size_t)tok*512;
    float v[16];
    float s = 0.f, s2 = 0.f;
    #pragma unroll
    for (int i = 0; i < 16; i++) { v[i] = row[lane + i*32]; s += v[i]; s2 = fmaf(v[i], v[i], s2); }
    #pragma unroll
    for (int o = 16; o; o >>= 1) {
        s  += __shfl_xor_sync(0xffffffffu, s,  o);
        s2 += __shfl_xor_sync(0xffffffffu, s2, o);
    }
    float m = s*(1.f/512.f);
    float r = rsqrtf(s2*(1.f/512.f) - m*m + 1e-5f);
    if (lane == 0) { g_mu[tok] = m; g_rs[tok] = r; }
    #pragma unroll
    for (int i = 0; i < 16; i++) {
        int k = lane + i*32;
        g_xq[(size_t)tok*512 + k] = (v[i] - m)*r*qg[k] + qb[k];
    }
}

// ===================== standalone attention (R2-validated) =====================
__global__ void attn_kernel_v15()
{
    int wid = threadIdx.x >> 5, lane = threadIdx.x & 31;
    int tok = blockIdx.x*4 + (wid >> 1);
    int h   = wid & 1;
    int b   = tok >> 12;
    const float* qrow = g_q + (size_t)tok*512 + h*256;
    const float* K0 = g_Kc + (size_t)(b*2+0)*512 + h*256;
    const float* K1 = g_Kc + (size_t)(b*2+1)*512 + h*256;
    float s0 = 0.f, s1 = 0.f;
    for (int d = lane; d < 256; d += 32) {
        float qv = qrow[d];
        s0 = fmaf(qv, K0[d], s0);
        s1 = fmaf(qv, K1[d], s1);
    }
    #pragma unroll
    for (int o = 16; o; o >>= 1) {
        s0 += __shfl_xor_sync(0xffffffffu, s0, o);
        s1 += __shfl_xor_sync(0xffffffffu, s1, o);
    }
    s0 *= 0.0625f; s1 *= 0.0625f;
    float mx = fmaxf(s0, s1);
    float e0 = expf(s0 - mx), e1 = expf(s1 - mx);
    float inv = 1.f/(e0 + e1);
    float p0 = e0*inv, p1 = e1*inv;
    const float* V0 = g_Vc + (size_t)(b*2+0)*512 + h*256;
    const float* V1 = g_Vc + (size_t)(b*2+1)*512 + h*256;
    for (int d = lane; d < 256; d += 32)
        g_a[(size_t)tok*512 + h*256 + d] = p0*V0[d] + p1*V1[d];
}

// ===================== elementwise: p = x*ao =====================
__global__ void p_kernel_v15(const float* __restrict__ x)
{
    size_t i = (size_t)blockIdx.x*256 + threadIdx.x;
    g_p[i] = x[i] * g_ao[i];
}

// ===================== LN kernels =====================
template<int W>
__global__ void ln_kernel_v15(const float* __restrict__ gv, const float* __restrict__ bv, float* __restrict__ outp)
{
    int tok = blockIdx.x*8 + (threadIdx.x >> 5);
    int lane = threadIdx.x & 31;
    const float* in = (W == 0) ? g_ucpre : g_pre;
    float* out = (W == 0) ? g_ucn : outp;
    const float* row = in + (size_t)tok*512;
    float v[16];
    float s = 0.f, s2 = 0.f;
    #pragma unroll
    for (int i = 0; i < 16; i++) { v[i] = row[lane + i*32]; s += v[i]; s2 = fmaf(v[i], v[i], s2); }
    #pragma unroll
    for (int o = 16; o; o >>= 1) {
        s  += __shfl_xor_sync(0xffffffffu, s,  o);
        s2 += __shfl_xor_sync(0xffffffffu, s2, o);
    }
    float m = s*(1.f/512.f);
    float r = rsqrtf(s2*(1.f/512.f) - m*m + 1e-5f);
    #pragma unroll
    for (int i = 0; i < 16; i++) {
        int k = lane + i*32;
        out[(size_t)tok*512 + k] = (v[i] - m)*r*gv[k] + bv[k];
    }
}

// ===================== GEMM slice: fp16, K=512, chunk=64, double-buffered, 512 threads =====================
// Row = 64 halves (128B) + 16B pad = 144B.
#define RB3     144
#define APL     (128*RB3)
#define BPL     (256*RB3)
#define OFF_A   0
#define OFF_B   (2*APL)
#define OFF_EPI (OFF_B + 2*BPL)
#define GSMEM   (OFF_EPI + 1536*4 + 256)

// EPI: 1=UC 2=Q 3=AO 4=WRITE 7=ADD 5=HRELU(prev+acc+bias, canary) 6=FINAL
template<int EPI, int BSTR, int AROW, int OSTR, int NOFF>
__global__ void __launch_bounds__(512, 1)
gemm_v15(const float* __restrict__ pA, const __half* __restrict__ pB,
         const float* __restrict__ bias, float* __restrict__ pOut,
         const float* __restrict__ prev, const float* __restrict__ xp,
         const unsigned int* __restrict__ pm,
         const float* __restrict__ flng, const float* __restrict__ flnb)
{
    extern __shared__ char smem[];
    uint32_t sb = smem_u32(smem);
    float* sEpi = (float*)(smem + OFF_EPI);

    const int tid = threadIdx.x;
    const int wid = tid >> 5, lane = tid & 31;
    const int gid = lane >> 2, tg = lane & 3;
    const int wm = wid >> 2, wn = wid & 3;       // 16 warps: 4x4 (M 32-row x N 64-col tiles)
    const int tok0 = blockIdx.x * 128;
    const int n0   = NOFF + blockIdx.y * 256;
    const int b    = tok0 >> 12;

    float acc[2][8][4];
    #pragma unroll
    for (int mt = 0; mt < 2; mt++)
        #pragma unroll
        for (int nt = 0; nt < 8; nt++)
            #pragma unroll
            for (int r = 0; r < 4; r++) acc[mt][nt][r] = 0.f;

    auto issueB = [&](int c, int buf) {
        const int kb = c*64;
        #pragma unroll
        for (int it = 0; it < 4; it++) {
            int u = tid + it*512;          // 2048 uint4 slots: 256 rows x 8
            int r = u >> 3, q = u & 7;
            cpa16(sb + OFF_B + (uint32_t)(buf*BPL + r*RB3 + q*16),
                  pB + (size_t)(n0 + r)*BSTR + kb + q*8);
        }
        CP_COMMIT();
    };
    auto loadA = [&](int c, float4* areg) {
        const int kb = c*64;
        #pragma unroll
        for (int it = 0; it < 4; it++) {
            int u = tid + it*512;          // 2048 float4 slots: 128 rows x 16
            int r = u >> 4, q = u & 15;
            areg[it] = *(const float4*)(pA + (size_t)(tok0 + r)*AROW + kb + q*4);
        }
    };
    auto storeA = [&](int buf, const float4* areg) {
        #pragma unroll
        for (int it = 0; it < 4; it++) {
            int u = tid + it*512;
            int r = u >> 4, q = u & 15;
            float4 va = areg[it];
            *(uint2*)(smem + OFF_A + (uint32_t)(buf*APL + r*RB3 + q*8))
                = make_uint2(pkh(va.x, va.y), pkh(va.z, va.w));
        }
    };

    // prologue
    {
        float4 areg[4];
        loadA(0, areg);
        issueB(0, 0);
        storeA(0, areg);
    }

    for (int c = 0; c < 8; c++) {
        const int buf = c & 1;
        CP_WAIT0();
        __syncthreads();

        float4 areg[4];
        if (c < 7) {
            issueB(c+1, buf^1);
            loadA(c+1, areg);
        }

        #pragma unroll
        for (int ks = 0; ks < 64; ks += 16) {
            uint32_t bh[8][2];
            #pragma unroll
            for (int nt = 0; nt < 8; nt++) {
                uint32_t o0 = OFF_B + (uint32_t)(buf*BPL + (wn*64 + nt*8 + gid)*RB3 + (ks + tg*2)*2);
                bh[nt][0] = *(const uint32_t*)(smem + o0);
                bh[nt][1] = *(const uint32_t*)(smem + o0 + 16);
            }
            #pragma unroll
            for (int mt = 0; mt < 2; mt++) {
                uint32_t oh = OFF_A + (uint32_t)(buf*APL + (wm*32 + mt*16 + gid)*RB3 + (ks + tg*2)*2);
                uint32_t ah[4];
                ah[0] = *(const uint32_t*)(smem + oh);
                ah[1] = *(const uint32_t*)(smem + oh + 8*RB3);
                ah[2] = *(const uint32_t*)(smem + oh + 16);
                ah[3] = *(const uint32_t*)(smem + oh + 8*RB3 + 16);
                #pragma unroll
                for (int nt = 0; nt < 8; nt++)
                    MMA_F16(acc[mt][nt], ah, bh[nt]);
            }
        }

        if (c < 7) storeA(buf^1, areg);
    }
    __syncthreads();

    // epilogue preloads
    if (EPI == 1) {
        if (tid < 256) sEpi[tid] = g_cbF[b*512 + n0 + tid];
    } else if (EPI == 2 || EPI == 3 || EPI == 5) {
        if (tid < 256) sEpi[tid] = bias[n0 + tid];
    } else if (EPI == 6) {
        if (tid < 256) {
            sEpi[tid]        = bias[n0 + tid];           // mix_b2
            sEpi[256 + tid]  = g_gam[b*512 + n0 + tid];
            sEpi[512 + tid]  = g_bet[b*512 + n0 + tid];
            sEpi[768 + tid]  = g_gate[b*512 + n0 + tid];
            sEpi[1024 + tid] = flng[n0 + tid];
            sEpi[1280 + tid] = flnb[n0 + tid];
        }
    }
    __syncthreads();

    #pragma unroll
    for (int mt = 0; mt < 2; mt++) {
        #pragma unroll
        for (int rh = 0; rh < 2; rh++) {
            int tok = tok0 + wm*32 + mt*16 + gid + rh*8;
            float muv = 0.f, rsv = 0.f, mskv = 0.f;
            if (EPI == 6) {
                muv = g_mu[tok]; rsv = g_rs[tok];
                mskv = (pm[tok] != 0u) ? 1.f : 0.f;
            }
            #pragma unroll
            for (int nt = 0; nt < 8; nt++) {
                #pragma unroll
                for (int rb = 0; rb < 2; rb++) {
                    int nl = wn*64 + nt*8 + tg*2 + rb;
                    float av = acc[mt][nt][rh*2 + rb];
                    if (EPI == 1) {
                        g_ucpre[(size_t)tok*512 + n0 + nl] = fmaxf(av + sEpi[nl], 0.f);
                    } else if (EPI == 2) {
                        g_q[(size_t)tok*512 + n0 + nl] = av + sEpi[nl];
                    } else if (EPI == 3) {
                        g_ao[(size_t)tok*512 + n0 + nl] = av + sEpi[nl];
                    } else if (EPI == 4) {
                        pOut[(size_t)tok*OSTR + n0 + nl] = av;
                    } else if (EPI == 7) {
                        pOut[(size_t)tok*OSTR + n0 + nl] += av;
                    } else if (EPI == 5) {
                        size_t gi = (size_t)tok*OSTR + n0 + nl;
                        float v = prev[gi] + av + sEpi[nl];
                        if (v != v) v = 1e20f;                 // NaN canary
                        else        v = fmaxf(v, 0.f);
                        pOut[gi] = v;
                    } else {  // EPI 6: final combine
                        size_t gi = (size_t)tok*512 + n0 + nl;
                        float ua = prev[gi] + av + sEpi[nl];
                        float xv = xp[gi];
                        float xh = (xv - muv)*rsv;
                        float base = sEpi[256 + nl]*fmaf(xh, sEpi[1024 + nl], sEpi[1280 + nl]) + sEpi[512 + nl];
                        g_pre[gi] = base + sEpi[768 + nl]*mskv*(g_ucn[gi] + ua);
                    }
                }
            }
        }
    }
}

// ===================== launch =====================
extern "C" void kernel_launch(void* const* d_in, const int* in_sizes, int n_in,
                              void* d_out, int out_size) {
    const float* x          = (const float*)d_in[0];
    const float* context    = (const float*)d_in[1];
    const unsigned int* mask = (const unsigned int*)d_in[2];
    const float* film_ln_g  = (const float*)d_in[3];
    const float* film_ln_b  = (const float*)d_in[4];
    const float* film_w     = (const float*)d_in[5];
    const float* film_b     = (const float*)d_in[6];
    const float* concat_w   = (const float*)d_in[7];
    const float* concat_b   = (const float*)d_in[8];
    const float* concat_ln_g= (const float*)d_in[9];
    const float* concat_ln_b= (const float*)d_in[10];
    const float* ctx_w1     = (const float*)d_in[11];
    const float* ctx_b1     = (const float*)d_in[12];
    const float* ctx_w2     = (const float*)d_in[13];
    const float* ctx_b2     = (const float*)d_in[14];
    const float* q_ln_g     = (const float*)d_in[15];
    const float* q_ln_b     = (const float*)d_in[16];
    const float* in_proj_w  = (const float*)d_in[17];
    const float* in_proj_b  = (const float*)d_in[18];
    const float* out_proj_w = (const float*)d_in[19];
    const float* out_proj_b = (const float*)d_in[20];
    const float* mix_w1     = (const float*)d_in[21];
    const float* mix_b1     = (const float*)d_in[22];
    const float* mix_w2     = (const float*)d_in[23];
    const float* mix_b2     = (const float*)d_in[24];
    const float* out_ln_g   = (const float*)d_in[25];
    const float* out_ln_b   = (const float*)d_in[26];
    const float* gate_w     = (const float*)d_in[27];
    const float* gate_b     = (const float*)d_in[28];
    float* out = (float*)d_out;

    float* t_ptr;  cudaGetSymbolAddress((void**)&t_ptr,  g_t);
    float* t2_ptr; cudaGetSymbolAddress((void**)&t2_ptr, g_t2);
    float* h_ptr;  cudaGetSymbolAddress((void**)&h_ptr,  g_h);
    float* xq_ptr; cudaGetSymbolAddress((void**)&xq_ptr, g_xq);
    float* a_ptr;  cudaGetSymbolAddress((void**)&a_ptr,  g_a);
    float* ao_ptr; cudaGetSymbolAddress((void**)&ao_ptr, g_ao);
    float* p_ptr;  cudaGetSymbolAddress((void**)&p_ptr,  g_p);
    __half *wcx, *wq, *wo, *w1f, *w2;
    cudaGetSymbolAddress((void**)&wcx, g_wcx);
    cudaGetSymbolAddress((void**)&wq,  g_wq);
    cudaGetSymbolAddress((void**)&wo,  g_wo);
    cudaGetSymbolAddress((void**)&w1f, g_w1f);
    cudaGetSymbolAddress((void**)&w2,  g_w2);

    #define SETSM(K) cudaFuncSetAttribute(K, cudaFuncAttributeMaxDynamicSharedMemorySize, GSMEM)
    SETSM((gemm_v15<1,512,512,512,0>));
    SETSM((gemm_v15<2,512,512,512,0>));
    SETSM((gemm_v15<3,512,512,512,0>));
    SETSM((gemm_v15<4,1536,512,1024,0>));   SETSM((gemm_v15<4,1536,512,1024,512>));
    SETSM((gemm_v15<7,1536,512,1024,0>));   SETSM((gemm_v15<7,1536,512,1024,512>));
    SETSM((gemm_v15<5,1536,512,1024,0>));   SETSM((gemm_v15<5,1536,512,1024,512>));
    SETSM((gemm_v15<4,1024,1024,512,0>));
    SETSM((gemm_v15<6,1024,1024,512,0>));

    // weight preprocessing (fp16; fold W1 in fp32 then convert)
    cvt_cwx_v15<<<(512*512)/256, 256>>>(concat_w);
    cvt_plain_v15<<<(512*512)/256, 256>>>(in_proj_w, wq, 512*512);    // rows 0..511 = Wq
    cvt_plain_v15<<<(512*512)/256, 256>>>(out_proj_w, wo, 512*512);
    fold_w1_v15<<<(1024*1536)/256, 256>>>(mix_w1);
    cvt_plain_v15<<<(512*1024)/256, 256>>>(mix_w2, w2, 512*1024);

    ctx_kernel_v15<<<Bm, 256>>>(context, film_w, film_b, ctx_w1, ctx_b1, ctx_w2, ctx_b2,
                                in_proj_w, in_proj_b, gate_w, gate_b, concat_w, concat_b);
    prep_x_v15<<<MT/8, 256>>>(x, q_ln_g, q_ln_b);

    dim3 G(256, 2);
    // G1: ucpre = relu(x @ Wcx^T + cbF)
    gemm_v15<1,512,512,512,0><<<G, 512, GSMEM>>>(x, wcx, nullptr, nullptr, nullptr, nullptr, nullptr, nullptr, nullptr);
    ln_kernel_v15<0><<<MT/8, 256>>>(concat_ln_g, concat_ln_b, nullptr);
    // G2: q
    gemm_v15<2,512,512,512,0><<<G, 512, GSMEM>>>(xq_ptr, wq, in_proj_b, nullptr, nullptr, nullptr, nullptr, nullptr, nullptr);
    attn_kernel_v15<<<MT/4, 256>>>();
    // G3: ao
    gemm_v15<3,512,512,512,0><<<G, 512, GSMEM>>>(a_ptr, wo, out_proj_b, nullptr, nullptr, nullptr, nullptr, nullptr, nullptr);
    p_kernel_v15<<<(MT*512)/256, 256>>>(x);

    // G4 (folded): h = relu(Wf0·x + Wf1·ao + Wf2·p + mb1), 3 K-slices x 2 N-halves
    gemm_v15<4,1536,512,1024,0>  <<<G, 512, GSMEM>>>(x, w1f,        nullptr, t_ptr, nullptr, nullptr, nullptr, nullptr, nullptr);
    gemm_v15<4,1536,512,1024,512><<<G, 512, GSMEM>>>(x, w1f,        nullptr, t_ptr, nullptr, nullptr, nullptr, nullptr, nullptr);
    gemm_v15<7,1536,512,1024,0>  <<<G, 512, GSMEM>>>(ao_ptr, w1f+512,  nullptr, t_ptr, nullptr, nullptr, nullptr, nullptr, nullptr);
    gemm_v15<7,1536,512,1024,512><<<G, 512, GSMEM>>>(ao_ptr, w1f+512,  nullptr, t_ptr, nullptr, nullptr, nullptr, nullptr, nullptr);
    gemm_v15<5,1536,512,1024,0>  <<<G, 512, GSMEM>>>(p_ptr, w1f+1024, mix_b1, h_ptr, t_ptr, nullptr, nullptr, nullptr, nullptr);
    gemm_v15<5,1536,512,1024,512><<<G, 512, GSMEM>>>(p_ptr, w1f+1024, mix_b1, h_ptr, t_ptr, nullptr, nullptr, nullptr, nullptr);

    // G5: 2 K-slices; slice1 carries final combine
    gemm_v15<4,1024,1024,512,0><<<G, 512, GSMEM>>>(h_ptr, w2, nullptr, t2_ptr, nullptr, nullptr, nullptr, nullptr, nullptr);
    gemm_v15<6,1024,1024,512,0><<<G, 512, GSMEM>>>(h_ptr + 512, w2 + 512, mix_b2, nullptr, t2_ptr, x, mask, film_ln_g, film_ln_b);
    ln_kernel_v15<1><<<MT/8, 256>>>(out_ln_g, out_ln_b, out);
}

// round 17
// speedup vs baseline: 5.1251x; 1.1479x over previous
#include <cuda_runtime.h>
#include <cuda_fp16.h>
#include <cstdint>
#include <math.h>

#define MT 32768
#define Cm 256
#define Bm 8

// ===================== helpers =====================
__device__ __forceinline__ uint32_t smem_u32(const void* p) {
    uint32_t a;
    asm("{ .reg .u64 t; cvta.to.shared.u64 t, %1; cvt.u32.u64 %0, t; }" : "=r"(a) : "l"(p));
    return a;
}
__device__ __forceinline__ void cpa16(uint32_t s, const void* g) {
    asm volatile("cp.async.cg.shared.global [%0], [%1], 16;" :: "r"(s), "l"(g));
}
#define CP_COMMIT() asm volatile("cp.async.commit_group;" ::: "memory")
#define CP_WAIT0()  asm volatile("cp.async.wait_group 0;" ::: "memory")

#define MMA_F16(C, A, B) asm volatile( \
    "mma.sync.aligned.m16n8k16.row.col.f32.f16.f16.f32 " \
    "{%0,%1,%2,%3}, {%4,%5,%6,%7}, {%8,%9}, {%0,%1,%2,%3};" \
    : "+f"((C)[0]), "+f"((C)[1]), "+f"((C)[2]), "+f"((C)[3]) \
    : "r"((A)[0]), "r"((A)[1]), "r"((A)[2]), "r"((A)[3]), "r"((B)[0]), "r"((B)[1]))

// ===================== device global scratch =====================
// fp16 activations (rounding identical to old storeA path)
__device__ __half g_xh[MT*512];     // half(x)
__device__ __half g_xqh[MT*512];    // half(x_q)
__device__ __half g_ah[MT*512];     // half(attn a)
__device__ __half g_aoh[MT*512];    // half(ao)
__device__ __half g_ph[MT*512];     // half(x*ao)
__device__ __half g_hh[MT*1024];    // half(h)
// fp32 state
__device__ float g_q[MT*512];
__device__ float g_t[MT*1024];      // G4 partial accumulator
__device__ float g_t2[MT*512];      // G5 partial accumulator
__device__ float g_ucpre[MT*512], g_ucn[MT*512], g_pre[MT*512];
__device__ float g_mu[MT], g_rs[MT];
__device__ float g_cbF[Bm*512], g_gam[Bm*512], g_bet[Bm*512], g_gate[Bm*512];
__device__ float g_Kc[Bm*2*512], g_Vc[Bm*2*512];
// fp16 weights
__device__ __half g_wcx[512*512];
__device__ __half g_wq[512*512];
__device__ __half g_wo[512*512];
__device__ __half g_w1f[1024*1536];   // folded mix_w1: [Wa+Wc | Wb-Wc | Wd]
__device__ __half g_w2[512*1024];

// ===================== weight preprocessing =====================
__global__ void cvt_plain_v16(const float* __restrict__ src, __half* dst, int n) {
    int i = blockIdx.x*blockDim.x + threadIdx.x;
    if (i >= n) return;
    dst[i] = __float2half_rn(src[i]);
}
__global__ void cvt_cwx_v16(const float* __restrict__ cw) {
    int i = blockIdx.x*blockDim.x + threadIdx.x;
    if (i >= 512*512) return;
    int r = i >> 9, c = i & 511;
    g_wcx[i] = __float2half_rn(cw[r*768 + c]);
}
__global__ void fold_w1_v16(const float* __restrict__ w1) {
    int i = blockIdx.x*blockDim.x + threadIdx.x;
    if (i >= 1024*1536) return;
    int j = i / 1536, k = i - j*1536;
    const float* row = w1 + (size_t)j*2048;
    float v;
    if (k < 512)       v = row[k] + row[1024+k];
    else if (k < 1024) v = row[k] - row[512+k];
    else               v = row[512+k];
    g_w1f[i] = __float2half_rn(v);
}

// ===================== per-batch context pipeline (R2-validated) =====================
__global__ void ctx_kernel_v16(const float* __restrict__ ctx,
    const float* __restrict__ film_w, const float* __restrict__ film_b,
    const float* __restrict__ w1, const float* __restrict__ b1,
    const float* __restrict__ w2, const float* __restrict__ b2,
    const float* __restrict__ inw, const float* __restrict__ inb,
    const float* __restrict__ gw, const float* __restrict__ gb,
    const float* __restrict__ cw, const float* __restrict__ cb)
{
    __shared__ float sc[Cm];
    __shared__ float sh[512];
    __shared__ float st[1024];
    int b = blockIdx.x, tid = threadIdx.x;
    if (tid < Cm) sc[tid] = ctx[b*Cm + tid];
    __syncthreads();
    for (int j = tid; j < 1024; j += 256) {
        const float* w = film_w + (size_t)j*Cm;
        float s = film_b[j];
        #pragma unroll 4
        for (int c = 0; c < Cm; c++) s = fmaf(w[c], sc[c], s);
        if (j < 512) g_gam[b*512 + j] = 1.f + s;
        else         g_bet[b*512 + (j-512)] = s;
    }
    for (int d = tid; d < 512; d += 256) {
        const float* w = gw + (size_t)d*Cm;
        float s = gb[d];
        #pragma unroll 4
        for (int c = 0; c < Cm; c++) s = fmaf(w[c], sc[c], s);
        g_gate[b*512 + d] = 1.f/(1.f + expf(-s));
    }
    for (int n = tid; n < 512; n += 256) {
        const float* w = cw + (size_t)n*768 + 512;
        float s = cb[n];
        #pragma unroll 4
        for (int c = 0; c < Cm; c++) s = fmaf(w[c], sc[c], s);
        g_cbF[b*512 + n] = s;
    }
    for (int i = tid; i < 512; i += 256) {
        const float* w = w1 + (size_t)i*Cm;
        float s = b1[i];
        #pragma unroll 4
        for (int c = 0; c < Cm; c++) s = fmaf(w[c], sc[c], s);
        sh[i] = 0.5f*s*(1.f + erff(s*0.70710678118654752f));
    }
    __syncthreads();
    for (int m = tid; m < 1024; m += 256) {
        const float* w = w2 + (size_t)m*512;
        float s = b2[m];
        #pragma unroll 4
        for (int e = 0; e < 512; e++) s = fmaf(w[e], sh[e], s);
        st[m] = s;
    }
    __syncthreads();
    for (int d = tid; d < 512; d += 256) {
        const float* wk = inw + (size_t)(512 + d)*512;
        const float* wv = inw + (size_t)(1024 + d)*512;
        float k0 = inb[512 + d], k1 = k0;
        float v0 = inb[1024 + d], v1 = v0;
        #pragma unroll 4
        for (int e = 0; e < 512; e++) {
            float a = wk[e], c = wv[e];
            k0 = fmaf(a, st[e],     k0);
            k1 = fmaf(a, st[512+e], k1);
            v0 = fmaf(c, st[e],     v0);
            v1 = fmaf(c, st[512+e], v1);
        }
        g_Kc[(b*2+0)*512 + d] = k0; g_Kc[(b*2+1)*512 + d] = k1;
        g_Vc[(b*2+0)*512 + d] = v0; g_Vc[(b*2+1)*512 + d] = v1;
    }
}

// ===================== prologue: LN stats + x_q + fp16 copies =====================
__global__ void prep_x_v16(const float* __restrict__ x,
                           const float* __restrict__ qg, const float* __restrict__ qb)
{
    int tok = blockIdx.x*8 + (threadIdx.x >> 5);
    int lane = threadIdx.x & 31;
    const float* row = x + (size_t)tok*512;
    float v[16];
    float s = 0.f, s2 = 0.f;
    #pragma unroll
    for (int i = 0; i < 16; i++) { v[i] = row[lane + i*32]; s += v[i]; s2 = fmaf(v[i], v[i], s2); }
    #pragma unroll
    for (int o = 16; o; o >>= 1) {
        s  += __shfl_xor_sync(0xffffffffu, s,  o);
        s2 += __shfl_xor_sync(0xffffffffu, s2, o);
    }
    float m = s*(1.f/512.f);
    float r = rsqrtf(s2*(1.f/512.f) - m*m + 1e-5f);
    if (lane == 0) { g_mu[tok] = m; g_rs[tok] = r; }
    #pragma unroll
    for (int i = 0; i < 16; i++) {
        int k = lane + i*32;
        size_t idx = (size_t)tok*512 + k;
        g_xh[idx] = __float2half_rn(v[i]);
        float xq = (v[i] - m)*r*qg[k] + qb[k];
        g_xqh[idx] = __float2half_rn(xq);
    }
}

// ===================== standalone attention (R2-validated) =====================
__global__ void attn_kernel_v16()
{
    int wid = threadIdx.x >> 5, lane = threadIdx.x & 31;
    int tok = blockIdx.x*4 + (wid >> 1);
    int h   = wid & 1;
    int b   = tok >> 12;
    const float* qrow = g_q + (size_t)tok*512 + h*256;
    const float* K0 = g_Kc + (size_t)(b*2+0)*512 + h*256;
    const float* K1 = g_Kc + (size_t)(b*2+1)*512 + h*256;
    float s0 = 0.f, s1 = 0.f;
    for (int d = lane; d < 256; d += 32) {
        float qv = qrow[d];
        s0 = fmaf(qv, K0[d], s0);
        s1 = fmaf(qv, K1[d], s1);
    }
    #pragma unroll
    for (int o = 16; o; o >>= 1) {
        s0 += __shfl_xor_sync(0xffffffffu, s0, o);
        s1 += __shfl_xor_sync(0xffffffffu, s1, o);
    }
    s0 *= 0.0625f; s1 *= 0.0625f;
    float mx = fmaxf(s0, s1);
    float e0 = expf(s0 - mx), e1 = expf(s1 - mx);
    float inv = 1.f/(e0 + e1);
    float p0 = e0*inv, p1 = e1*inv;
    const float* V0 = g_Vc + (size_t)(b*2+0)*512 + h*256;
    const float* V1 = g_Vc + (size_t)(b*2+1)*512 + h*256;
    for (int d = lane; d < 256; d += 32)
        g_ah[(size_t)tok*512 + h*256 + d] = __float2half_rn(p0*V0[d] + p1*V1[d]);
}

// ===================== LN kernels =====================
template<int W>
__global__ void ln_kernel_v16(const float* __restrict__ gv, const float* __restrict__ bv, float* __restrict__ outp)
{
    int tok = blockIdx.x*8 + (threadIdx.x >> 5);
    int lane = threadIdx.x & 31;
    const float* in = (W == 0) ? g_ucpre : g_pre;
    float* out = (W == 0) ? g_ucn : outp;
    const float* row = in + (size_t)tok*512;
    float v[16];
    float s = 0.f, s2 = 0.f;
    #pragma unroll
    for (int i = 0; i < 16; i++) { v[i] = row[lane + i*32]; s += v[i]; s2 = fmaf(v[i], v[i], s2); }
    #pragma unroll
    for (int o = 16; o; o >>= 1) {
        s  += __shfl_xor_sync(0xffffffffu, s,  o);
        s2 += __shfl_xor_sync(0xffffffffu, s2, o);
    }
    float m = s*(1.f/512.f);
    float r = rsqrtf(s2*(1.f/512.f) - m*m + 1e-5f);
    #pragma unroll
    for (int i = 0; i < 16; i++) {
        int k = lane + i*32;
        out[(size_t)tok*512 + k] = (v[i] - m)*r*gv[k] + bv[k];
    }
}

// ===================== GEMM slice: fp16 A+B via cp.async, K=512, chunk=64, M128xN128, 2 CTA/SM =====================
#define RB3     144
#define APL     (128*RB3)
#define BPL     (128*RB3)
#define OFF_A   0
#define OFF_B   (2*APL)
#define OFF_EPI (OFF_B + 2*BPL)
#define GSMEM   (OFF_EPI + 768*4 + 128)

// EPI: 1=UC 2=Q 3=AO(+p fused) 4=WRITE 7=ADD 5=HRELU(prev+acc+bias, canary) 6=FINAL
template<int EPI, int BSTR, int AROW, int OSTR>
__global__ void __launch_bounds__(256, 2)
gemm_v16(const __half* __restrict__ pA, const __half* __restrict__ pB,
         const float* __restrict__ bias, float* __restrict__ pOut,
         const float* __restrict__ prev, const float* __restrict__ xp,
         const unsigned int* __restrict__ pm,
         const float* __restrict__ flng, const float* __restrict__ flnb)
{
    extern __shared__ char smem[];
    uint32_t sb = smem_u32(smem);
    float* sEpi = (float*)(smem + OFF_EPI);

    const int tid = threadIdx.x;
    const int wid = tid >> 5, lane = tid & 31;
    const int gid = lane >> 2, tg = lane & 3;
    const int wm = wid >> 1, wn = wid & 1;       // 8 warps: 4(M) x 2(N); warp tile 32x64
    const int tok0 = blockIdx.x * 128;
    const int n0   = blockIdx.y * 128;
    const int b    = tok0 >> 12;

    float acc[2][8][4];
    #pragma unroll
    for (int mt = 0; mt < 2; mt++)
        #pragma unroll
        for (int nt = 0; nt < 8; nt++)
            #pragma unroll
            for (int r = 0; r < 4; r++) acc[mt][nt][r] = 0.f;

    auto issue = [&](int c, int buf) {
        const int kb = c*64;
        #pragma unroll
        for (int it = 0; it < 4; it++) {     // A: 128 rows x 8 uint4
            int u = tid + it*256;
            int r = u >> 3, q = u & 7;
            cpa16(sb + OFF_A + (uint32_t)(buf*APL + r*RB3 + q*16),
                  pA + (size_t)(tok0 + r)*AROW + kb + q*8);
        }
        #pragma unroll
        for (int it = 0; it < 4; it++) {     // B: 128 rows x 8 uint4
            int u = tid + it*256;
            int r = u >> 3, q = u & 7;
            cpa16(sb + OFF_B + (uint32_t)(buf*BPL + r*RB3 + q*16),
                  pB + (size_t)(n0 + r)*BSTR + kb + q*8);
        }
        CP_COMMIT();
    };

    issue(0, 0);
    for (int c = 0; c < 8; c++) {
        const int buf = c & 1;
        CP_WAIT0();
        __syncthreads();
        if (c < 7) issue(c+1, buf^1);

        #pragma unroll
        for (int ks = 0; ks < 64; ks += 16) {
            uint32_t bh[8][2];
            #pragma unroll
            for (int nt = 0; nt < 8; nt++) {
                uint32_t o0 = OFF_B + (uint32_t)(buf*BPL + (wn*64 + nt*8 + gid)*RB3 + (ks + tg*2)*2);
                bh[nt][0] = *(const uint32_t*)(smem + o0);
                bh[nt][1] = *(const uint32_t*)(smem + o0 + 16);
            }
            #pragma unroll
            for (int mt = 0; mt < 2; mt++) {
                uint32_t oh = OFF_A + (uint32_t)(buf*APL + (wm*32 + mt*16 + gid)*RB3 + (ks + tg*2)*2);
                uint32_t ah[4];
                ah[0] = *(const uint32_t*)(smem + oh);
                ah[1] = *(const uint32_t*)(smem + oh + 8*RB3);
                ah[2] = *(const uint32_t*)(smem + oh + 16);
                ah[3] = *(const uint32_t*)(smem + oh + 8*RB3 + 16);
                #pragma unroll
                for (int nt = 0; nt < 8; nt++)
                    MMA_F16(acc[mt][nt], ah, bh[nt]);
            }
        }
    }
    __syncthreads();

    // epilogue preloads (128 floats per section)
    if (EPI == 1) {
        if (tid < 128) sEpi[tid] = g_cbF[b*512 + n0 + tid];
    } else if (EPI == 2 || EPI == 3 || EPI == 5) {
        if (tid < 128) sEpi[tid] = bias[n0 + tid];
    } else if (EPI == 6) {
        if (tid < 128) {
            sEpi[tid]       = bias[n0 + tid];            // mix_b2
            sEpi[128 + tid] = g_gam[b*512 + n0 + tid];
            sEpi[256 + tid] = g_bet[b*512 + n0 + tid];
            sEpi[384 + tid] = g_gate[b*512 + n0 + tid];
            sEpi[512 + tid] = flng[n0 + tid];
            sEpi[640 + tid] = flnb[n0 + tid];
        }
    }
    __syncthreads();

    #pragma unroll
    for (int mt = 0; mt < 2; mt++) {
        #pragma unroll
        for (int rh = 0; rh < 2; rh++) {
            int tok = tok0 + wm*32 + mt*16 + gid + rh*8;
            float muv = 0.f, rsv = 0.f, mskv = 0.f;
            if (EPI == 6) {
                muv = g_mu[tok]; rsv = g_rs[tok];
                mskv = (pm[tok] != 0u) ? 1.f : 0.f;
            }
            #pragma unroll
            for (int nt = 0; nt < 8; nt++) {
                #pragma unroll
                for (int rb = 0; rb < 2; rb++) {
                    int nl = wn*64 + nt*8 + tg*2 + rb;
                    float av = acc[mt][nt][rh*2 + rb];
                    if (EPI == 1) {
                        g_ucpre[(size_t)tok*512 + n0 + nl] = fmaxf(av + sEpi[nl], 0.f);
                    } else if (EPI == 2) {
                        g_q[(size_t)tok*512 + n0 + nl] = av + sEpi[nl];
                    } else if (EPI == 3) {
                        size_t gi = (size_t)tok*512 + n0 + nl;
                        float ao = av + sEpi[nl];
                        float xv = xp[gi];
                        g_aoh[gi] = __float2half_rn(ao);
                        g_ph[gi]  = __float2half_rn(xv*ao);
                    } else if (EPI == 4) {
                        pOut[(size_t)tok*OSTR + n0 + nl] = av;
                    } else if (EPI == 7) {
                        pOut[(size_t)tok*OSTR + n0 + nl] += av;
                    } else if (EPI == 5) {
                        size_t gi = (size_t)tok*OSTR + n0 + nl;
                        float v = prev[gi] + av + sEpi[nl];
                        if (v != v) v = 1e20f;                 // NaN canary
                        else        v = fmaxf(v, 0.f);
                        g_hh[gi] = __float2half_rn(v);
                    } else {  // EPI 6: final combine
                        size_t gi = (size_t)tok*512 + n0 + nl;
                        float ua = prev[gi] + av + sEpi[nl];
                        float xv = xp[gi];
                        float xh = (xv - muv)*rsv;
                        float base = sEpi[128 + nl]*fmaf(xh, sEpi[512 + nl], sEpi[640 + nl]) + sEpi[256 + nl];
                        g_pre[gi] = base + sEpi[384 + nl]*mskv*(g_ucn[gi] + ua);
                    }
                }
            }
        }
    }
}

// ===================== launch =====================
extern "C" void kernel_launch(void* const* d_in, const int* in_sizes, int n_in,
                              void* d_out, int out_size) {
    const float* x          = (const float*)d_in[0];
    const float* context    = (const float*)d_in[1];
    const unsigned int* mask = (const unsigned int*)d_in[2];
    const float* film_ln_g  = (const float*)d_in[3];
    const float* film_ln_b  = (const float*)d_in[4];
    const float* film_w     = (const float*)d_in[5];
    const float* film_b     = (const float*)d_in[6];
    const float* concat_w   = (const float*)d_in[7];
    const float* concat_b   = (const float*)d_in[8];
    const float* concat_ln_g= (const float*)d_in[9];
    const float* concat_ln_b= (const float*)d_in[10];
    const float* ctx_w1     = (const float*)d_in[11];
    const float* ctx_b1     = (const float*)d_in[12];
    const float* ctx_w2     = (const float*)d_in[13];
    const float* ctx_b2     = (const float*)d_in[14];
    const float* q_ln_g     = (const float*)d_in[15];
    const float* q_ln_b     = (const float*)d_in[16];
    const float* in_proj_w  = (const float*)d_in[17];
    const float* in_proj_b  = (const float*)d_in[18];
    const float* out_proj_w = (const float*)d_in[19];
    const float* out_proj_b = (const float*)d_in[20];
    const float* mix_w1     = (const float*)d_in[21];
    const float* mix_b1     = (const float*)d_in[22];
    const float* mix_w2     = (const float*)d_in[23];
    const float* mix_b2     = (const float*)d_in[24];
    const float* out_ln_g   = (const float*)d_in[25];
    const float* out_ln_b   = (const float*)d_in[26];
    const float* gate_w     = (const float*)d_in[27];
    const float* gate_b     = (const float*)d_in[28];
    float* out = (float*)d_out;

    float* t_ptr;  cudaGetSymbolAddress((void**)&t_ptr,  g_t);
    float* t2_ptr; cudaGetSymbolAddress((void**)&t2_ptr, g_t2);
    __half *xh, *xqh, *ah, *aoh, *ph, *hh;
    cudaGetSymbolAddress((void**)&xh,  g_xh);
    cudaGetSymbolAddress((void**)&xqh, g_xqh);
    cudaGetSymbolAddress((void**)&ah,  g_ah);
    cudaGetSymbolAddress((void**)&aoh, g_aoh);
    cudaGetSymbolAddress((void**)&ph,  g_ph);
    cudaGetSymbolAddress((void**)&hh,  g_hh);
    __half *wcx, *wq, *wo, *w1f, *w2;
    cudaGetSymbolAddress((void**)&wcx, g_wcx);
    cudaGetSymbolAddress((void**)&wq,  g_wq);
    cudaGetSymbolAddress((void**)&wo,  g_wo);
    cudaGetSymbolAddress((void**)&w1f, g_w1f);
    cudaGetSymbolAddress((void**)&w2,  g_w2);

    #define SETSM(K) cudaFuncSetAttribute(K, cudaFuncAttributeMaxDynamicSharedMemorySize, GSMEM)
    SETSM((gemm_v16<1,512,512,512>));
    SETSM((gemm_v16<2,512,512,512>));
    SETSM((gemm_v16<3,512,512,512>));
    SETSM((gemm_v16<4,1536,512,1024>));
    SETSM((gemm_v16<7,1536,512,1024>));
    SETSM((gemm_v16<5,1536,512,1024>));
    SETSM((gemm_v16<4,1024,1024,512>));
    SETSM((gemm_v16<6,1024,1024,512>));

    // weight preprocessing
    cvt_cwx_v16<<<(512*512)/256, 256>>>(concat_w);
    cvt_plain_v16<<<(512*512)/256, 256>>>(in_proj_w, wq, 512*512);
    cvt_plain_v16<<<(512*512)/256, 256>>>(out_proj_w, wo, 512*512);
    fold_w1_v16<<<(1024*1536)/256, 256>>>(mix_w1);
    cvt_plain_v16<<<(512*1024)/256, 256>>>(mix_w2, w2, 512*1024);

    ctx_kernel_v16<<<Bm, 256>>>(context, film_w, film_b, ctx_w1, ctx_b1, ctx_w2, ctx_b2,
                                in_proj_w, in_proj_b, gate_w, gate_b, concat_w, concat_b);
    prep_x_v16<<<MT/8, 256>>>(x, q_ln_g, q_ln_b);

    // G1: ucpre = relu(x @ Wcx^T + cbF)
    gemm_v16<1,512,512,512><<<dim3(256,4), 256, GSMEM>>>(xh, wcx, nullptr, nullptr, nullptr, nullptr, nullptr, nullptr, nullptr);
    ln_kernel_v16<0><<<MT/8, 256>>>(concat_ln_g, concat_ln_b, nullptr);
    // G2: q
    gemm_v16<2,512,512,512><<<dim3(256,4), 256, GSMEM>>>(xqh, wq, in_proj_b, nullptr, nullptr, nullptr, nullptr, nullptr, nullptr);
    attn_kernel_v16<<<MT/4, 256>>>();
    // G3: ao (+p fused)
    gemm_v16<3,512,512,512><<<dim3(256,4), 256, GSMEM>>>(ah, wo, out_proj_b, nullptr, nullptr, x, nullptr, nullptr, nullptr);

    // G4 (folded): h = relu(Wf0·x + Wf1·ao + Wf2·p + mb1), 3 K-slices, N=1024 via grid.y=8
    gemm_v16<4,1536,512,1024><<<dim3(256,8), 256, GSMEM>>>(xh,  w1f,      nullptr, t_ptr, nullptr, nullptr, nullptr, nullptr, nullptr);
    gemm_v16<7,1536,512,1024><<<dim3(256,8), 256, GSMEM>>>(aoh, w1f+512,  nullptr, t_ptr, nullptr, nullptr, nullptr, nullptr, nullptr);
    gemm_v16<5,1536,512,1024><<<dim3(256,8), 256, GSMEM>>>(ph,  w1f+1024, mix_b1,  nullptr, t_ptr, nullptr, nullptr, nullptr, nullptr);

    // G5: 2 K-slices; slice1 carries final combine
    gemm_v16<4,1024,1024,512><<<dim3(256,4), 256, GSMEM>>>(hh, w2, nullptr, t2_ptr, nullptr, nullptr, nullptr, nullptr, nullptr);
    gemm_v16<6,1024,1024,512><<<dim3(256,4), 256, GSMEM>>>(hh + 512, w2 + 512, mix_b2, nullptr, t2_ptr, x, mask, film_ln_g, film_ln_b);
    ln_kernel_v16<1><<<MT/8, 256>>>(out_ln_g, out_ln_b, out);
}